// round 2
// baseline (speedup 1.0000x reference)
#include <cuda_runtime.h>
#include <cstdint>

// ---------------------------------------------------------------------------
// Problem constants
// ---------------------------------------------------------------------------
#define NTOK   204800          // B*T*V = 64*128*25
#define DMODEL 256
#define NGRP   8192            // B*T
#define VTOK   25
#define NHEAD  8
#define HDIM   32

// ---------------------------------------------------------------------------
// Device scratch (static; no allocation allowed)
// ---------------------------------------------------------------------------
__device__ float g_y   [(size_t)NTOK * 256];
__device__ float g_qkv [(size_t)NTOK * 768];
__device__ float g_ao  [(size_t)NTOK * 256];
__device__ float g_xf  [(size_t)NTOK * 256];
__device__ float g_y2  [(size_t)NTOK * 256];
__device__ float g_h   [(size_t)NTOK * 1024];

// ---------------------------------------------------------------------------
// Helpers
// ---------------------------------------------------------------------------
__device__ __forceinline__ unsigned f2tf32(float f) {
    unsigned u;
    asm("cvt.rna.tf32.f32 %0, %1;" : "=r"(u) : "f"(f));
    return u;
}

__device__ __forceinline__ void mma_tf32(float* d, const unsigned* a, const unsigned* b) {
    asm volatile(
        "mma.sync.aligned.m16n8k8.row.col.f32.tf32.tf32.f32 "
        "{%0,%1,%2,%3}, {%4,%5,%6,%7}, {%8,%9}, {%0,%1,%2,%3};"
        : "+f"(d[0]), "+f"(d[1]), "+f"(d[2]), "+f"(d[3])
        : "r"(a[0]), "r"(a[1]), "r"(a[2]), "r"(a[3]), "r"(b[0]), "r"(b[1]));
}

__device__ __forceinline__ float gelu_exact(float x) {
    return 0.5f * x * (1.0f + erff(x * 0.70710678118654752f));
}

// ---------------------------------------------------------------------------
// LayerNorm: one warp per row of 256
// ---------------------------------------------------------------------------
__global__ __launch_bounds__(256)
void ln_kernel(const float* __restrict__ x, const float* __restrict__ g,
               const float* __restrict__ b, float* __restrict__ y)
{
    int row  = blockIdx.x * 8 + (threadIdx.x >> 5);
    int lane = threadIdx.x & 31;
    const float* xr = x + (size_t)row * 256;

    float4 v0 = *(const float4*)(xr + lane * 4);
    float4 v1 = *(const float4*)(xr + 128 + lane * 4);

    float s = v0.x + v0.y + v0.z + v0.w + v1.x + v1.y + v1.z + v1.w;
    #pragma unroll
    for (int o = 16; o; o >>= 1) s += __shfl_xor_sync(0xFFFFFFFFu, s, o);
    float mean = s * (1.0f / 256.0f);

    float d0 = v0.x - mean, d1 = v0.y - mean, d2 = v0.z - mean, d3 = v0.w - mean;
    float d4 = v1.x - mean, d5 = v1.y - mean, d6 = v1.z - mean, d7 = v1.w - mean;
    float vs = d0*d0 + d1*d1 + d2*d2 + d3*d3 + d4*d4 + d5*d5 + d6*d6 + d7*d7;
    #pragma unroll
    for (int o = 16; o; o >>= 1) vs += __shfl_xor_sync(0xFFFFFFFFu, vs, o);
    float rstd = rsqrtf(vs * (1.0f / 256.0f) + 1e-5f);

    float4 g0 = *(const float4*)(g + lane * 4);
    float4 g1 = *(const float4*)(g + 128 + lane * 4);
    float4 b0 = *(const float4*)(b + lane * 4);
    float4 b1 = *(const float4*)(b + 128 + lane * 4);

    float* yr = y + (size_t)row * 256;
    float4 o0, o1;
    o0.x = d0 * rstd * g0.x + b0.x;  o0.y = d1 * rstd * g0.y + b0.y;
    o0.z = d2 * rstd * g0.z + b0.z;  o0.w = d3 * rstd * g0.w + b0.w;
    o1.x = d4 * rstd * g1.x + b1.x;  o1.y = d5 * rstd * g1.y + b1.y;
    o1.z = d6 * rstd * g1.z + b1.z;  o1.w = d7 * rstd * g1.w + b1.w;
    *(float4*)(yr + lane * 4)       = o0;
    *(float4*)(yr + 128 + lane * 4) = o1;
}

// ---------------------------------------------------------------------------
// tf32 GEMM: C[M,N] = A[M,K] @ B[K,N]  (both row-major) with epilogue
//   EPI 1: + bias
//   EPI 2: + bias, exact GELU
//   EPI 3: + bias + residual
// CTA tile 128x128x32, 8 warps each 64x32 (2x4 warp grid), mma m16n8k8.
// ---------------------------------------------------------------------------
#define AS_STRIDE 36
#define BS_STRIDE 132

template<int EPI>
__global__ __launch_bounds__(256)
void gemm_tf32(const float* __restrict__ A, const float* __restrict__ B,
               const float* __restrict__ bias, const float* __restrict__ resid,
               float* __restrict__ C, int N, int K)
{
    __shared__ unsigned sA[128 * AS_STRIDE];
    __shared__ unsigned sB[32 * BS_STRIDE];

    int tid  = threadIdx.x;
    int w    = tid >> 5;
    int lane = tid & 31;
    int gid  = lane >> 2;
    int tig  = lane & 3;
    int wm   = w >> 2;      // 0..1
    int wn   = w & 3;       // 0..3

    long mBase = (long)blockIdx.y * 128;
    int  nBase = blockIdx.x * 128;

    float acc[4][4][4];
    #pragma unroll
    for (int mt = 0; mt < 4; mt++)
        #pragma unroll
        for (int nt = 0; nt < 4; nt++)
            #pragma unroll
            for (int c = 0; c < 4; c++) acc[mt][nt][c] = 0.0f;

    int arow = tid >> 3, ac4 = tid & 7;    // A: rows arow + i*32, col4 ac4
    int brow = tid >> 5, bc4 = tid & 31;   // B: rows brow + i*8,  col4 bc4

    for (int k0 = 0; k0 < K; k0 += 32) {
        #pragma unroll
        for (int i = 0; i < 4; i++) {
            int r = arow + i * 32;
            float4 v = *(const float4*)(A + (mBase + r) * (long)K + k0 + ac4 * 4);
            uint4 u;
            u.x = f2tf32(v.x); u.y = f2tf32(v.y); u.z = f2tf32(v.z); u.w = f2tf32(v.w);
            *(uint4*)(sA + r * AS_STRIDE + ac4 * 4) = u;
        }
        #pragma unroll
        for (int i = 0; i < 4; i++) {
            int kr = brow + i * 8;
            float4 v = *(const float4*)(B + (long)(k0 + kr) * N + nBase + bc4 * 4);
            uint4 u;
            u.x = f2tf32(v.x); u.y = f2tf32(v.y); u.z = f2tf32(v.z); u.w = f2tf32(v.w);
            *(uint4*)(sB + kr * BS_STRIDE + bc4 * 4) = u;
        }
        __syncthreads();

        #pragma unroll
        for (int ks = 0; ks < 4; ks++) {
            unsigned af[4][4];
            unsigned bf[4][2];
            int kc = ks * 8 + tig;
            #pragma unroll
            for (int mt = 0; mt < 4; mt++) {
                int mr = wm * 64 + mt * 16 + gid;
                af[mt][0] = sA[mr * AS_STRIDE + kc];
                af[mt][1] = sA[(mr + 8) * AS_STRIDE + kc];
                af[mt][2] = sA[mr * AS_STRIDE + kc + 4];
                af[mt][3] = sA[(mr + 8) * AS_STRIDE + kc + 4];
            }
            #pragma unroll
            for (int nt = 0; nt < 4; nt++) {
                int nc = wn * 32 + nt * 8 + gid;
                bf[nt][0] = sB[kc * BS_STRIDE + nc];
                bf[nt][1] = sB[(kc + 4) * BS_STRIDE + nc];
            }
            #pragma unroll
            for (int mt = 0; mt < 4; mt++)
                #pragma unroll
                for (int nt = 0; nt < 4; nt++)
                    mma_tf32(acc[mt][nt], af[mt], bf[nt]);
        }
        __syncthreads();
    }

    // Epilogue
    #pragma unroll
    for (int mt = 0; mt < 4; mt++) {
        long r0 = mBase + wm * 64 + mt * 16 + gid;
        long r1 = r0 + 8;
        #pragma unroll
        for (int nt = 0; nt < 4; nt++) {
            int cb = nBase + wn * 32 + nt * 8 + tig * 2;
            float bb0 = bias[cb], bb1 = bias[cb + 1];
            float c0 = acc[mt][nt][0] + bb0;
            float c1 = acc[mt][nt][1] + bb1;
            float c2 = acc[mt][nt][2] + bb0;
            float c3 = acc[mt][nt][3] + bb1;
            if (EPI == 2) {
                c0 = gelu_exact(c0); c1 = gelu_exact(c1);
                c2 = gelu_exact(c2); c3 = gelu_exact(c3);
            }
            if (EPI == 3) {
                float2 ra = *(const float2*)(resid + r0 * N + cb);
                float2 rb = *(const float2*)(resid + r1 * N + cb);
                c0 += ra.x; c1 += ra.y; c2 += rb.x; c3 += rb.y;
            }
            float2 o0; o0.x = c0; o0.y = c1;
            float2 o1; o1.x = c2; o1.y = c3;
            *(float2*)(C + r0 * N + cb) = o0;
            *(float2*)(C + r1 * N + cb) = o1;
        }
    }
}

// ---------------------------------------------------------------------------
// Cosine attention. One block = (group, half); 4 warps = 4 heads.
// smem stages q,k,v slices for those 4 heads: 25 rows x 384 cols (+4 pad).
// Warp layout: lane i (<25) owns query row i; k/v rows read via smem broadcast.
// ---------------------------------------------------------------------------
#define SQ_STRIDE 388

__global__ __launch_bounds__(128)
void attn_kernel(const float* __restrict__ qkv, const float* __restrict__ ls,
                 float* __restrict__ ao)
{
    __shared__ float sq[VTOK * SQ_STRIDE];

    int g    = blockIdx.x >> 1;
    int half = blockIdx.x & 1;
    int tid  = threadIdx.x;

    // Stage q,k,v slices for this half's 4 heads: per token-row, 3 sections
    // (q/k/v) x 128 floats (4 heads x 32 dims) = 96 float4s per row.
    const float* src = qkv + (size_t)g * VTOK * 768 + half * 128;
    for (int idx = tid; idx < VTOK * 96; idx += 128) {
        int r = idx / 96, rem = idx % 96;
        int s = rem >> 5, c4 = rem & 31;
        float4 v = *(const float4*)(src + (size_t)r * 768 + s * 256 + c4 * 4);
        *(float4*)(sq + r * SQ_STRIDE + s * 128 + c4 * 4) = v;
    }
    __syncthreads();

    int w    = tid >> 5;
    int lane = tid & 31;
    int h    = half * 4 + w;

    float scale = __expf(fminf(ls[h], 4.60517018598809f));   // log(100)

    // normalize this head's K rows in place (lane j handles row j)
    if (lane < VTOK) {
        float* kr = sq + lane * SQ_STRIDE + 128 + w * 32;
        float kv[32];
        float ss = 0.0f;
        #pragma unroll
        for (int c = 0; c < 8; c++) {
            float4 t4 = *(const float4*)(kr + c * 4);
            kv[c*4+0] = t4.x; kv[c*4+1] = t4.y; kv[c*4+2] = t4.z; kv[c*4+3] = t4.w;
            ss += t4.x*t4.x + t4.y*t4.y + t4.z*t4.z + t4.w*t4.w;
        }
        float inv = 1.0f / fmaxf(sqrtf(ss), 1e-12f);
        #pragma unroll
        for (int c = 0; c < 8; c++) {
            float4 t4;
            t4.x = kv[c*4+0]*inv; t4.y = kv[c*4+1]*inv;
            t4.z = kv[c*4+2]*inv; t4.w = kv[c*4+3]*inv;
            *(float4*)(kr + c * 4) = t4;
        }
    }
    __syncwarp();

    // load + normalize query row (lane i)
    int i = lane < VTOK ? lane : 0;
    const float* qr = sq + i * SQ_STRIDE + w * 32;
    float q[32];
    float ss = 0.0f;
    #pragma unroll
    for (int c = 0; c < 8; c++) {
        float4 t4 = *(const float4*)(qr + c * 4);
        q[c*4+0] = t4.x; q[c*4+1] = t4.y; q[c*4+2] = t4.z; q[c*4+3] = t4.w;
        ss += t4.x*t4.x + t4.y*t4.y + t4.z*t4.z + t4.w*t4.w;
    }
    // fold cosine scale and sdpa 1/sqrt(hd) into q
    float qf = scale / (5.65685424949238f * fmaxf(sqrtf(ss), 1e-12f));
    #pragma unroll
    for (int d = 0; d < 32; d++) q[d] *= qf;

    // logits (lane-local row of 25)
    float p[VTOK];
    #pragma unroll
    for (int j = 0; j < VTOK; j++) {
        const float* kr = sq + j * SQ_STRIDE + 128 + w * 32;   // broadcast
        float a = 0.0f;
        #pragma unroll
        for (int c = 0; c < 8; c++) {
            float4 k4 = *(const float4*)(kr + c * 4);
            a += q[c*4+0]*k4.x + q[c*4+1]*k4.y + q[c*4+2]*k4.z + q[c*4+3]*k4.w;
        }
        p[j] = a;
    }

    // softmax (lane-local)
    float m = p[0];
    #pragma unroll
    for (int j = 1; j < VTOK; j++) m = fmaxf(m, p[j]);
    float s = 0.0f;
    #pragma unroll
    for (int j = 0; j < VTOK; j++) { p[j] = __expf(p[j] - m); s += p[j]; }
    float invs = 1.0f / s;

    // out = P @ V
    float o[32];
    #pragma unroll
    for (int d = 0; d < 32; d++) o[d] = 0.0f;
    #pragma unroll
    for (int j = 0; j < VTOK; j++) {
        const float* vr = sq + j * SQ_STRIDE + 256 + w * 32;   // broadcast
        float pj = p[j] * invs;
        #pragma unroll
        for (int c = 0; c < 8; c++) {
            float4 v4 = *(const float4*)(vr + c * 4);
            o[c*4+0] += pj * v4.x; o[c*4+1] += pj * v4.y;
            o[c*4+2] += pj * v4.z; o[c*4+3] += pj * v4.w;
        }
    }

    if (lane < VTOK) {
        float* dst = ao + ((size_t)g * VTOK + lane) * 256 + h * 32;
        #pragma unroll
        for (int c = 0; c < 8; c++) {
            float4 t4;
            t4.x = o[c*4+0]; t4.y = o[c*4+1]; t4.z = o[c*4+2]; t4.w = o[c*4+3];
            *(float4*)(dst + c * 4) = t4;
        }
    }
}

// ---------------------------------------------------------------------------
// Launch
// ---------------------------------------------------------------------------
extern "C" void kernel_launch(void* const* d_in, const int* in_sizes, int n_in,
                              void* d_out, int out_size)
{
    const float* x       = (const float*)d_in[0];
    const float* ln1_g   = (const float*)d_in[1];
    const float* ln1_b   = (const float*)d_in[2];
    const float* qkv_w   = (const float*)d_in[3];
    const float* qkv_b   = (const float*)d_in[4];
    const float* proj_w  = (const float*)d_in[5];
    const float* proj_b  = (const float*)d_in[6];
    const float* lscale  = (const float*)d_in[7];
    const float* ln2_g   = (const float*)d_in[8];
    const float* ln2_b   = (const float*)d_in[9];
    const float* ffn_w1  = (const float*)d_in[10];
    const float* ffn_b1  = (const float*)d_in[11];
    const float* ffn_w2  = (const float*)d_in[12];
    const float* ffn_b2  = (const float*)d_in[13];

    float *y, *qkv, *ao, *xf, *y2, *h;
    cudaGetSymbolAddress((void**)&y,   g_y);
    cudaGetSymbolAddress((void**)&qkv, g_qkv);
    cudaGetSymbolAddress((void**)&ao,  g_ao);
    cudaGetSymbolAddress((void**)&xf,  g_xf);
    cudaGetSymbolAddress((void**)&y2,  g_y2);
    cudaGetSymbolAddress((void**)&h,   g_h);

    // 1) LN1
    ln_kernel<<<NTOK / 8, 256>>>(x, ln1_g, ln1_b, y);
    // 2) QKV = y @ Wqkv + b
    gemm_tf32<1><<<dim3(6, NTOK / 128), 256>>>(y, qkv_w, qkv_b, nullptr, qkv, 768, 256);
    // 3) cosine attention
    attn_kernel<<<NGRP * 2, 128>>>(qkv, lscale, ao);
    // 4) xf = ao @ Wproj + b + x
    gemm_tf32<3><<<dim3(2, NTOK / 128), 256>>>(ao, proj_w, proj_b, x, xf, 256, 256);
    // 5) LN2
    ln_kernel<<<NTOK / 8, 256>>>(xf, ln2_g, ln2_b, y2);
    // 6) h = gelu(y2 @ W1 + b1)
    gemm_tf32<2><<<dim3(8, NTOK / 128), 256>>>(y2, ffn_w1, ffn_b1, nullptr, h, 1024, 256);
    // 7) out = h @ W2 + b2 + xf
    gemm_tf32<3><<<dim3(2, NTOK / 128), 256>>>(h, ffn_w2, ffn_b2, xf, (float*)d_out, 256, 1024);
}

// round 3
// speedup vs baseline: 1.0769x; 1.0769x over previous
#include <cuda_runtime.h>
#include <cstdint>

// ---------------------------------------------------------------------------
// Problem constants
// ---------------------------------------------------------------------------
#define NTOK   204800          // B*T*V = 64*128*25
#define DMODEL 256
#define NGRP   8192            // B*T
#define VTOK   25
#define NHEAD  8
#define HDIM   32

// ---------------------------------------------------------------------------
// Device scratch (static; no allocation allowed)
// ---------------------------------------------------------------------------
__device__ float g_y   [(size_t)NTOK * 256];
__device__ float g_qkv [(size_t)NTOK * 768];
__device__ float g_ao  [(size_t)NTOK * 256];
__device__ float g_xf  [(size_t)NTOK * 256];
__device__ float g_y2  [(size_t)NTOK * 256];
__device__ float g_h   [(size_t)NTOK * 1024];

// ---------------------------------------------------------------------------
// Helpers
// ---------------------------------------------------------------------------
__device__ __forceinline__ unsigned f2tf32(float f) {
    unsigned u;
    asm("cvt.rna.tf32.f32 %0, %1;" : "=r"(u) : "f"(f));
    return u;
}

__device__ __forceinline__ void mma_tf32(float* d, const unsigned* a, const unsigned* b) {
    asm volatile(
        "mma.sync.aligned.m16n8k8.row.col.f32.tf32.tf32.f32 "
        "{%0,%1,%2,%3}, {%4,%5,%6,%7}, {%8,%9}, {%0,%1,%2,%3};"
        : "+f"(d[0]), "+f"(d[1]), "+f"(d[2]), "+f"(d[3])
        : "r"(a[0]), "r"(a[1]), "r"(a[2]), "r"(a[3]), "r"(b[0]), "r"(b[1]));
}

__device__ __forceinline__ void cp16(unsigned dst, const void* src) {
    asm volatile("cp.async.cg.shared.global [%0], [%1], 16;" :: "r"(dst), "l"(src));
}
#define CP_COMMIT() asm volatile("cp.async.commit_group;")
#define CP_WAIT1()  asm volatile("cp.async.wait_group 1;")

__device__ __forceinline__ float gelu_exact(float x) {
    return 0.5f * x * (1.0f + erff(x * 0.70710678118654752f));
}

// ---------------------------------------------------------------------------
// LayerNorm: one warp per row of 256
// ---------------------------------------------------------------------------
__global__ __launch_bounds__(256)
void ln_kernel(const float* __restrict__ x, const float* __restrict__ g,
               const float* __restrict__ b, float* __restrict__ y)
{
    int row  = blockIdx.x * 8 + (threadIdx.x >> 5);
    int lane = threadIdx.x & 31;
    const float* xr = x + (size_t)row * 256;

    float4 v0 = *(const float4*)(xr + lane * 4);
    float4 v1 = *(const float4*)(xr + 128 + lane * 4);

    float s = v0.x + v0.y + v0.z + v0.w + v1.x + v1.y + v1.z + v1.w;
    #pragma unroll
    for (int o = 16; o; o >>= 1) s += __shfl_xor_sync(0xFFFFFFFFu, s, o);
    float mean = s * (1.0f / 256.0f);

    float d0 = v0.x - mean, d1 = v0.y - mean, d2 = v0.z - mean, d3 = v0.w - mean;
    float d4 = v1.x - mean, d5 = v1.y - mean, d6 = v1.z - mean, d7 = v1.w - mean;
    float vs = d0*d0 + d1*d1 + d2*d2 + d3*d3 + d4*d4 + d5*d5 + d6*d6 + d7*d7;
    #pragma unroll
    for (int o = 16; o; o >>= 1) vs += __shfl_xor_sync(0xFFFFFFFFu, vs, o);
    float rstd = rsqrtf(vs * (1.0f / 256.0f) + 1e-5f);

    float4 g0 = *(const float4*)(g + lane * 4);
    float4 g1 = *(const float4*)(g + 128 + lane * 4);
    float4 b0 = *(const float4*)(b + lane * 4);
    float4 b1 = *(const float4*)(b + 128 + lane * 4);

    float* yr = y + (size_t)row * 256;
    float4 o0, o1;
    o0.x = d0 * rstd * g0.x + b0.x;  o0.y = d1 * rstd * g0.y + b0.y;
    o0.z = d2 * rstd * g0.z + b0.z;  o0.w = d3 * rstd * g0.w + b0.w;
    o1.x = d4 * rstd * g1.x + b1.x;  o1.y = d5 * rstd * g1.y + b1.y;
    o1.z = d6 * rstd * g1.z + b1.z;  o1.w = d7 * rstd * g1.w + b1.w;
    *(float4*)(yr + lane * 4)       = o0;
    *(float4*)(yr + 128 + lane * 4) = o1;
}

// ---------------------------------------------------------------------------
// tf32 GEMM v2: C[M,N] = A[M,K] @ B[K,N] (row-major) + epilogue
//   EPI 1: + bias | EPI 2: + bias, GELU | EPI 3: + bias + residual
// CTA 128x128, 4 warps (2x2) of 64x64 warp tiles; K-chunk 16;
// cp.async 2-stage double buffer; conflict-free smem strides.
// ---------------------------------------------------------------------------
#define A_PITCH 20              // 16 + 4 pad floats (80B, 16B aligned)
#define B_PITCH 136             // 128 + 8 pad floats (544B, 16B aligned)
#define A_ST    (128 * A_PITCH) // 2560 floats
#define B_ST    (16 * B_PITCH)  // 2176 floats
#define STAGE   (A_ST + B_ST)   // 4736 floats = 18944 B

template<int EPI>
__global__ __launch_bounds__(128, 2)
void gemm_tf32(const float* __restrict__ A, const float* __restrict__ B,
               const float* __restrict__ bias, const float* __restrict__ resid,
               float* __restrict__ C, int N, int K)
{
    __shared__ float sm[2 * STAGE];

    int tid  = threadIdx.x;
    int w    = tid >> 5;
    int lane = tid & 31;
    int gid  = lane >> 2;
    int tig  = lane & 3;
    int wm   = w >> 1;      // 0..1
    int wn   = w & 1;       // 0..1

    long mBase = (long)blockIdx.y * 128;
    int  nBase = blockIdx.x * 128;

    unsigned smBase = (unsigned)__cvta_generic_to_shared(sm);

    // cp.async index precompute
    // A: 512 chunks of 16B (128 rows x 4), thread does 4
    int a_row = tid >> 1;             // chunks c = tid + i*128: row=(c>>2)
    // we derive per-chunk inside the lambda-ish macro below instead
    const float* Abase = A + mBase * (long)K;
    const float* Bbase = B + nBase;

    float acc[4][8][4];
    #pragma unroll
    for (int mt = 0; mt < 4; mt++)
        #pragma unroll
        for (int nt = 0; nt < 8; nt++)
            #pragma unroll
            for (int c = 0; c < 4; c++) acc[mt][nt][c] = 0.0f;

    int T = K >> 4;

    // ---- stage loader ----
    #define LOAD_STAGE(buf, k0)                                                 \
    {                                                                           \
        unsigned sa = smBase + (unsigned)((buf) * STAGE) * 4u;                  \
        unsigned sb = sa + (unsigned)A_ST * 4u;                                 \
        _Pragma("unroll")                                                       \
        for (int i = 0; i < 4; i++) {                                           \
            int c  = tid + i * 128;                                             \
            int r  = c >> 2, c4 = c & 3;                                        \
            cp16(sa + (unsigned)(r * A_PITCH + c4 * 4) * 4u,                    \
                 Abase + (long)r * K + (k0) + c4 * 4);                          \
        }                                                                       \
        _Pragma("unroll")                                                       \
        for (int i = 0; i < 4; i++) {                                           \
            int c  = tid + i * 128;                                             \
            int r  = c >> 5, c4 = c & 31;                                       \
            cp16(sb + (unsigned)(r * B_PITCH + c4 * 4) * 4u,                    \
                 Bbase + (long)((k0) + r) * N + c4 * 4);                        \
        }                                                                       \
    }

    LOAD_STAGE(0, 0);
    CP_COMMIT();
    if (T > 1) LOAD_STAGE(1, 16);
    CP_COMMIT();

    for (int it = 0; it < T; it++) {
        CP_WAIT1();
        __syncthreads();

        const float* sa = sm + (it & 1) * STAGE;
        const float* sb = sa + A_ST;

        #pragma unroll
        for (int ks = 0; ks < 2; ks++) {
            int kc = ks * 8 + tig;
            unsigned af[4][4];
            #pragma unroll
            for (int mt = 0; mt < 4; mt++) {
                int mr = wm * 64 + mt * 16 + gid;
                af[mt][0] = f2tf32(sa[mr * A_PITCH + kc]);
                af[mt][1] = f2tf32(sa[(mr + 8) * A_PITCH + kc]);
                af[mt][2] = f2tf32(sa[mr * A_PITCH + kc + 4]);
                af[mt][3] = f2tf32(sa[(mr + 8) * A_PITCH + kc + 4]);
            }
            unsigned bf[8][2];
            #pragma unroll
            for (int nt = 0; nt < 8; nt++) {
                int nc = wn * 64 + nt * 8 + gid;
                bf[nt][0] = f2tf32(sb[kc * B_PITCH + nc]);
                bf[nt][1] = f2tf32(sb[(kc + 4) * B_PITCH + nc]);
            }
            #pragma unroll
            for (int mt = 0; mt < 4; mt++)
                #pragma unroll
                for (int nt = 0; nt < 8; nt++)
                    mma_tf32(acc[mt][nt], af[mt], bf[nt]);
        }

        __syncthreads();
        if (it + 2 < T) LOAD_STAGE(it & 1, (it + 2) * 16);
        CP_COMMIT();
    }

    // ---- epilogue ----
    #pragma unroll
    for (int mt = 0; mt < 4; mt++) {
        long r0 = mBase + wm * 64 + mt * 16 + gid;
        long r1 = r0 + 8;
        #pragma unroll
        for (int nt = 0; nt < 8; nt++) {
            int cb = nBase + wn * 64 + nt * 8 + tig * 2;
            float bb0 = bias[cb], bb1 = bias[cb + 1];
            float c0 = acc[mt][nt][0] + bb0;
            float c1 = acc[mt][nt][1] + bb1;
            float c2 = acc[mt][nt][2] + bb0;
            float c3 = acc[mt][nt][3] + bb1;
            if (EPI == 2) {
                c0 = gelu_exact(c0); c1 = gelu_exact(c1);
                c2 = gelu_exact(c2); c3 = gelu_exact(c3);
            }
            if (EPI == 3) {
                float2 ra = *(const float2*)(resid + r0 * N + cb);
                float2 rb = *(const float2*)(resid + r1 * N + cb);
                c0 += ra.x; c1 += ra.y; c2 += rb.x; c3 += rb.y;
            }
            float2 o0; o0.x = c0; o0.y = c1;
            float2 o1; o1.x = c2; o1.y = c3;
            *(float2*)(C + r0 * N + cb) = o0;
            *(float2*)(C + r1 * N + cb) = o1;
        }
    }
    #undef LOAD_STAGE
}

// ---------------------------------------------------------------------------
// Cosine attention. One block = (group, half); 4 warps = 4 heads.
// ---------------------------------------------------------------------------
#define SQ_STRIDE 388

__global__ __launch_bounds__(128)
void attn_kernel(const float* __restrict__ qkv, const float* __restrict__ ls,
                 float* __restrict__ ao)
{
    __shared__ float sq[VTOK * SQ_STRIDE];

    int g    = blockIdx.x >> 1;
    int half = blockIdx.x & 1;
    int tid  = threadIdx.x;

    const float* src = qkv + (size_t)g * VTOK * 768 + half * 128;
    for (int idx = tid; idx < VTOK * 96; idx += 128) {
        int r = idx / 96, rem = idx % 96;
        int s = rem >> 5, c4 = rem & 31;
        float4 v = *(const float4*)(src + (size_t)r * 768 + s * 256 + c4 * 4);
        *(float4*)(sq + r * SQ_STRIDE + s * 128 + c4 * 4) = v;
    }
    __syncthreads();

    int w    = tid >> 5;
    int lane = tid & 31;
    int h    = half * 4 + w;

    float scale = __expf(fminf(ls[h], 4.60517018598809f));   // log(100)

    if (lane < VTOK) {
        float* kr = sq + lane * SQ_STRIDE + 128 + w * 32;
        float kv[32];
        float ss = 0.0f;
        #pragma unroll
        for (int c = 0; c < 8; c++) {
            float4 t4 = *(const float4*)(kr + c * 4);
            kv[c*4+0] = t4.x; kv[c*4+1] = t4.y; kv[c*4+2] = t4.z; kv[c*4+3] = t4.w;
            ss += t4.x*t4.x + t4.y*t4.y + t4.z*t4.z + t4.w*t4.w;
        }
        float inv = 1.0f / fmaxf(sqrtf(ss), 1e-12f);
        #pragma unroll
        for (int c = 0; c < 8; c++) {
            float4 t4;
            t4.x = kv[c*4+0]*inv; t4.y = kv[c*4+1]*inv;
            t4.z = kv[c*4+2]*inv; t4.w = kv[c*4+3]*inv;
            *(float4*)(kr + c * 4) = t4;
        }
    }
    __syncwarp();

    int i = lane < VTOK ? lane : 0;
    const float* qr = sq + i * SQ_STRIDE + w * 32;
    float q[32];
    float ss = 0.0f;
    #pragma unroll
    for (int c = 0; c < 8; c++) {
        float4 t4 = *(const float4*)(qr + c * 4);
        q[c*4+0] = t4.x; q[c*4+1] = t4.y; q[c*4+2] = t4.z; q[c*4+3] = t4.w;
        ss += t4.x*t4.x + t4.y*t4.y + t4.z*t4.z + t4.w*t4.w;
    }
    float qf = scale / (5.65685424949238f * fmaxf(sqrtf(ss), 1e-12f));
    #pragma unroll
    for (int d = 0; d < 32; d++) q[d] *= qf;

    float p[VTOK];
    #pragma unroll
    for (int j = 0; j < VTOK; j++) {
        const float* kr = sq + j * SQ_STRIDE + 128 + w * 32;
        float a = 0.0f;
        #pragma unroll
        for (int c = 0; c < 8; c++) {
            float4 k4 = *(const float4*)(kr + c * 4);
            a += q[c*4+0]*k4.x + q[c*4+1]*k4.y + q[c*4+2]*k4.z + q[c*4+3]*k4.w;
        }
        p[j] = a;
    }

    float m = p[0];
    #pragma unroll
    for (int j = 1; j < VTOK; j++) m = fmaxf(m, p[j]);
    float s = 0.0f;
    #pragma unroll
    for (int j = 0; j < VTOK; j++) { p[j] = __expf(p[j] - m); s += p[j]; }
    float invs = 1.0f / s;

    float o[32];
    #pragma unroll
    for (int d = 0; d < 32; d++) o[d] = 0.0f;
    #pragma unroll
    for (int j = 0; j < VTOK; j++) {
        const float* vr = sq + j * SQ_STRIDE + 256 + w * 32;
        float pj = p[j] * invs;
        #pragma unroll
        for (int c = 0; c < 8; c++) {
            float4 v4 = *(const float4*)(vr + c * 4);
            o[c*4+0] += pj * v4.x; o[c*4+1] += pj * v4.y;
            o[c*4+2] += pj * v4.z; o[c*4+3] += pj * v4.w;
        }
    }

    if (lane < VTOK) {
        float* dst = ao + ((size_t)g * VTOK + lane) * 256 + h * 32;
        #pragma unroll
        for (int c = 0; c < 8; c++) {
            float4 t4;
            t4.x = o[c*4+0]; t4.y = o[c*4+1]; t4.z = o[c*4+2]; t4.w = o[c*4+3];
            *(float4*)(dst + c * 4) = t4;
        }
    }
}

// ---------------------------------------------------------------------------
// Launch
// ---------------------------------------------------------------------------
extern "C" void kernel_launch(void* const* d_in, const int* in_sizes, int n_in,
                              void* d_out, int out_size)
{
    const float* x       = (const float*)d_in[0];
    const float* ln1_g   = (const float*)d_in[1];
    const float* ln1_b   = (const float*)d_in[2];
    const float* qkv_w   = (const float*)d_in[3];
    const float* qkv_b   = (const float*)d_in[4];
    const float* proj_w  = (const float*)d_in[5];
    const float* proj_b  = (const float*)d_in[6];
    const float* lscale  = (const float*)d_in[7];
    const float* ln2_g   = (const float*)d_in[8];
    const float* ln2_b   = (const float*)d_in[9];
    const float* ffn_w1  = (const float*)d_in[10];
    const float* ffn_b1  = (const float*)d_in[11];
    const float* ffn_w2  = (const float*)d_in[12];
    const float* ffn_b2  = (const float*)d_in[13];

    float *y, *qkv, *ao, *xf, *y2, *h;
    cudaGetSymbolAddress((void**)&y,   g_y);
    cudaGetSymbolAddress((void**)&qkv, g_qkv);
    cudaGetSymbolAddress((void**)&ao,  g_ao);
    cudaGetSymbolAddress((void**)&xf,  g_xf);
    cudaGetSymbolAddress((void**)&y2,  g_y2);
    cudaGetSymbolAddress((void**)&h,   g_h);

    // 1) LN1
    ln_kernel<<<NTOK / 8, 256>>>(x, ln1_g, ln1_b, y);
    // 2) QKV = y @ Wqkv + b
    gemm_tf32<1><<<dim3(6, NTOK / 128), 128>>>(y, qkv_w, qkv_b, nullptr, qkv, 768, 256);
    // 3) cosine attention
    attn_kernel<<<NGRP * 2, 128>>>(qkv, lscale, ao);
    // 4) xf = ao @ Wproj + b + x
    gemm_tf32<3><<<dim3(2, NTOK / 128), 128>>>(ao, proj_w, proj_b, x, xf, 256, 256);
    // 5) LN2
    ln_kernel<<<NTOK / 8, 256>>>(xf, ln2_g, ln2_b, y2);
    // 6) h = gelu(y2 @ W1 + b1)
    gemm_tf32<2><<<dim3(8, NTOK / 128), 128>>>(y2, ffn_w1, ffn_b1, nullptr, h, 1024, 256);
    // 7) out = h @ W2 + b2 + xf
    gemm_tf32<3><<<dim3(2, NTOK / 128), 128>>>(h, ffn_w2, ffn_b2, xf, (float*)d_out, 256, 1024);
}

// round 6
// speedup vs baseline: 1.1005x; 1.0219x over previous
#include <cuda_runtime.h>
#include <cstdint>

// ---------------------------------------------------------------------------
// Problem constants
// ---------------------------------------------------------------------------
#define NTOK   204800          // B*T*V = 64*128*25
#define NGRP   8192            // B*T
#define VTOK   25

// ---------------------------------------------------------------------------
// Device scratch (static; no allocation allowed)
// ---------------------------------------------------------------------------
__device__ float g_y   [(size_t)NTOK * 256];
__device__ float g_qkv [(size_t)NTOK * 768];
__device__ float g_ao  [(size_t)NTOK * 256];
__device__ float g_xf  [(size_t)NTOK * 256];
__device__ float g_y2  [(size_t)NTOK * 256];
__device__ float g_h   [(size_t)NTOK * 1024];
// pre-rounded (tf32) weight copies: qkv_w | proj_w | ffn_w1 | ffn_w2
#define W_QKV  0
#define W_PROJ (256 * 768)
#define W_FFN1 (W_PROJ + 256 * 256)
#define W_FFN2 (W_FFN1 + 256 * 1024)
#define W_TOT  (W_FFN2 + 1024 * 256)
__device__ float g_w[(size_t)W_TOT];

// ---------------------------------------------------------------------------
// Helpers
// ---------------------------------------------------------------------------
__device__ __forceinline__ unsigned f2tf32(float f) {
    unsigned u;
    asm("cvt.rna.tf32.f32 %0, %1;" : "=r"(u) : "f"(f));
    return u;
}
__device__ __forceinline__ float tf32r(float f) {
    return __uint_as_float(f2tf32(f));
}

__device__ __forceinline__ void mma_tf32(float* d, const unsigned* a, const unsigned* b) {
    asm volatile(
        "mma.sync.aligned.m16n8k8.row.col.f32.tf32.tf32.f32 "
        "{%0,%1,%2,%3}, {%4,%5,%6,%7}, {%8,%9}, {%0,%1,%2,%3};"
        : "+f"(d[0]), "+f"(d[1]), "+f"(d[2]), "+f"(d[3])
        : "r"(a[0]), "r"(a[1]), "r"(a[2]), "r"(a[3]), "r"(b[0]), "r"(b[1]));
}

__device__ __forceinline__ void cp16(unsigned dst, const void* src) {
    asm volatile("cp.async.cg.shared.global [%0], [%1], 16;" :: "r"(dst), "l"(src));
}
#define CP_COMMIT() asm volatile("cp.async.commit_group;")
#define CP_WAIT1()  asm volatile("cp.async.wait_group 1;")

__device__ __forceinline__ float gelu_exact(float x) {
    return 0.5f * x * (1.0f + erff(x * 0.70710678118654752f));
}

// ---------------------------------------------------------------------------
// Weight pre-rounding to tf32 (rna), once per launch
// ---------------------------------------------------------------------------
__global__ __launch_bounds__(256)
void round_w_kernel(const float* __restrict__ src, float* __restrict__ dst, int n4)
{
    int i = blockIdx.x * 256 + threadIdx.x;
    if (i < n4) {
        float4 v = ((const float4*)src)[i];
        v.x = tf32r(v.x); v.y = tf32r(v.y); v.z = tf32r(v.z); v.w = tf32r(v.w);
        ((float4*)dst)[i] = v;
    }
}

// ---------------------------------------------------------------------------
// LayerNorm: one warp per row of 256. Output tf32-rounded (consumed as GEMM A).
// ---------------------------------------------------------------------------
__global__ __launch_bounds__(256)
void ln_kernel(const float* __restrict__ x, const float* __restrict__ g,
               const float* __restrict__ b, float* __restrict__ y)
{
    int row  = blockIdx.x * 8 + (threadIdx.x >> 5);
    int lane = threadIdx.x & 31;
    const float* xr = x + (size_t)row * 256;

    float4 v0 = *(const float4*)(xr + lane * 4);
    float4 v1 = *(const float4*)(xr + 128 + lane * 4);

    float s = v0.x + v0.y + v0.z + v0.w + v1.x + v1.y + v1.z + v1.w;
    #pragma unroll
    for (int o = 16; o; o >>= 1) s += __shfl_xor_sync(0xFFFFFFFFu, s, o);
    float mean = s * (1.0f / 256.0f);

    float d0 = v0.x - mean, d1 = v0.y - mean, d2 = v0.z - mean, d3 = v0.w - mean;
    float d4 = v1.x - mean, d5 = v1.y - mean, d6 = v1.z - mean, d7 = v1.w - mean;
    float vs = d0*d0 + d1*d1 + d2*d2 + d3*d3 + d4*d4 + d5*d5 + d6*d6 + d7*d7;
    #pragma unroll
    for (int o = 16; o; o >>= 1) vs += __shfl_xor_sync(0xFFFFFFFFu, vs, o);
    float rstd = rsqrtf(vs * (1.0f / 256.0f) + 1e-5f);

    float4 g0 = *(const float4*)(g + lane * 4);
    float4 g1 = *(const float4*)(g + 128 + lane * 4);
    float4 b0 = *(const float4*)(b + lane * 4);
    float4 b1 = *(const float4*)(b + 128 + lane * 4);

    float* yr = y + (size_t)row * 256;
    float4 o0, o1;
    o0.x = tf32r(d0 * rstd * g0.x + b0.x);  o0.y = tf32r(d1 * rstd * g0.y + b0.y);
    o0.z = tf32r(d2 * rstd * g0.z + b0.z);  o0.w = tf32r(d3 * rstd * g0.w + b0.w);
    o1.x = tf32r(d4 * rstd * g1.x + b1.x);  o1.y = tf32r(d5 * rstd * g1.y + b1.y);
    o1.z = tf32r(d6 * rstd * g1.z + b1.z);  o1.w = tf32r(d7 * rstd * g1.w + b1.w);
    *(float4*)(yr + lane * 4)       = o0;
    *(float4*)(yr + 128 + lane * 4) = o1;
}

// ---------------------------------------------------------------------------
// tf32 GEMM v3: C[M,N] = A[M,K] @ B[K,N] (row-major, operands pre-tf32-rounded)
//   EPI 1: + bias | EPI 2: + bias, GELU (output tf32-rounded) | EPI 3: + bias + residual
// CTA 128x128, 8 warps (2x4) of 64x32; K-chunk 16; cp.async double buffer.
// Inner loop: LDS + HMMA only (no cvt).
// ---------------------------------------------------------------------------
#define A_PITCH 20              // floats (80B rows, conflict-free frag reads)
#define B_PITCH 136             // floats (544B rows, conflict-free frag reads)
#define A_ST    (128 * A_PITCH) // 2560 floats
#define B_ST    (16 * B_PITCH)  // 2176 floats
#define STAGE   (A_ST + B_ST)   // 4736 floats = 18944 B

template<int EPI>
__global__ __launch_bounds__(256, 2)
void gemm_tf32(const float* __restrict__ A, const float* __restrict__ B,
               const float* __restrict__ bias, const float* __restrict__ resid,
               float* __restrict__ C, int N, int K)
{
    __shared__ float sm[2 * STAGE];

    int tid  = threadIdx.x;
    int w    = tid >> 5;
    int lane = tid & 31;
    int gid  = lane >> 2;
    int tig  = lane & 3;
    int wm   = w >> 2;      // 0..1
    int wn   = w & 3;       // 0..3

    long mBase = (long)blockIdx.y * 128;
    int  nBase = blockIdx.x * 128;

    unsigned smBase = (unsigned)__cvta_generic_to_shared(sm);
    const float* Abase = A + mBase * (long)K;
    const float* Bbase = B + nBase;

    float acc[4][4][4];
    #pragma unroll
    for (int mt = 0; mt < 4; mt++)
        #pragma unroll
        for (int nt = 0; nt < 4; nt++)
            #pragma unroll
            for (int c = 0; c < 4; c++) acc[mt][nt][c] = 0.0f;

    int T = K >> 4;

    // 512 16B-chunks per stage for A (128 rows x 4), 512 for B (16 rows x 32);
    // 256 threads -> 2 chunks each.
    #define LOAD_STAGE(buf, k0)                                                 \
    {                                                                           \
        unsigned sa = smBase + (unsigned)((buf) * STAGE) * 4u;                  \
        unsigned sb = sa + (unsigned)A_ST * 4u;                                 \
        _Pragma("unroll")                                                       \
        for (int i = 0; i < 2; i++) {                                           \
            int c  = tid + i * 256;                                             \
            int r  = c >> 2, c4 = c & 3;                                        \
            cp16(sa + (unsigned)(r * A_PITCH + c4 * 4) * 4u,                    \
                 Abase + (long)r * K + (k0) + c4 * 4);                          \
        }                                                                       \
        _Pragma("unroll")                                                       \
        for (int i = 0; i < 2; i++) {                                           \
            int c  = tid + i * 256;                                             \
            int r  = c >> 5, c4 = c & 31;                                       \
            cp16(sb + (unsigned)(r * B_PITCH + c4 * 4) * 4u,                    \
                 Bbase + (long)((k0) + r) * N + c4 * 4);                        \
        }                                                                       \
    }

    LOAD_STAGE(0, 0);
    CP_COMMIT();
    if (T > 1) LOAD_STAGE(1, 16);
    CP_COMMIT();

    for (int it = 0; it < T; it++) {
        CP_WAIT1();
        __syncthreads();

        const float* sa = sm + (it & 1) * STAGE;
        const float* sb = sa + A_ST;

        #pragma unroll
        for (int ks = 0; ks < 2; ks++) {
            int kc = ks * 8 + tig;
            unsigned af[4][4];
            #pragma unroll
            for (int mt = 0; mt < 4; mt++) {
                int mr = wm * 64 + mt * 16 + gid;
                af[mt][0] = __float_as_uint(sa[mr * A_PITCH + kc]);
                af[mt][1] = __float_as_uint(sa[(mr + 8) * A_PITCH + kc]);
                af[mt][2] = __float_as_uint(sa[mr * A_PITCH + kc + 4]);
                af[mt][3] = __float_as_uint(sa[(mr + 8) * A_PITCH + kc + 4]);
            }
            unsigned bf[4][2];
            #pragma unroll
            for (int nt = 0; nt < 4; nt++) {
                int nc = wn * 32 + nt * 8 + gid;
                bf[nt][0] = __float_as_uint(sb[kc * B_PITCH + nc]);
                bf[nt][1] = __float_as_uint(sb[(kc + 4) * B_PITCH + nc]);
            }
            #pragma unroll
            for (int mt = 0; mt < 4; mt++)
                #pragma unroll
                for (int nt = 0; nt < 4; nt++)
                    mma_tf32(acc[mt][nt], af[mt], bf[nt]);
        }

        __syncthreads();
        if (it + 2 < T) LOAD_STAGE(it & 1, (it + 2) * 16);
        CP_COMMIT();
    }

    // ---- epilogue ----
    #pragma unroll
    for (int mt = 0; mt < 4; mt++) {
        long r0 = mBase + wm * 64 + mt * 16 + gid;
        long r1 = r0 + 8;
        #pragma unroll
        for (int nt = 0; nt < 4; nt++) {
            int cb = nBase + wn * 32 + nt * 8 + tig * 2;
            float bb0 = bias[cb], bb1 = bias[cb + 1];
            float c0 = acc[mt][nt][0] + bb0;
            float c1 = acc[mt][nt][1] + bb1;
            float c2 = acc[mt][nt][2] + bb0;
            float c3 = acc[mt][nt][3] + bb1;
            if (EPI == 2) {   // GELU, output is next GEMM's A operand -> round
                c0 = tf32r(gelu_exact(c0)); c1 = tf32r(gelu_exact(c1));
                c2 = tf32r(gelu_exact(c2)); c3 = tf32r(gelu_exact(c3));
            }
            if (EPI == 3) {
                float2 ra = *(const float2*)(resid + r0 * N + cb);
                float2 rb = *(const float2*)(resid + r1 * N + cb);
                c0 += ra.x; c1 += ra.y; c2 += rb.x; c3 += rb.y;
            }
            float2 o0; o0.x = c0; o0.y = c1;
            float2 o1; o1.x = c2; o1.y = c3;
            *(float2*)(C + r0 * N + cb) = o0;
            *(float2*)(C + r1 * N + cb) = o1;
        }
    }
    #undef LOAD_STAGE
}

// ---------------------------------------------------------------------------
// Cosine attention. One block = (group, half); 4 warps = 4 heads.
// Output tf32-rounded (consumed as proj GEMM A operand).
// ---------------------------------------------------------------------------
#define SQ_STRIDE 388

__global__ __launch_bounds__(128)
void attn_kernel(const float* __restrict__ qkv, const float* __restrict__ ls,
                 float* __restrict__ ao)
{
    __shared__ float sq[VTOK * SQ_STRIDE];

    int g    = blockIdx.x >> 1;
    int half = blockIdx.x & 1;
    int tid  = threadIdx.x;

    const float* src = qkv + (size_t)g * VTOK * 768 + half * 128;
    for (int idx = tid; idx < VTOK * 96; idx += 128) {
        int r = idx / 96, rem = idx % 96;
        int s = rem >> 5, c4 = rem & 31;
        float4 v = *(const float4*)(src + (size_t)r * 768 + s * 256 + c4 * 4);
        *(float4*)(sq + r * SQ_STRIDE + s * 128 + c4 * 4) = v;
    }
    __syncthreads();

    int w    = tid >> 5;
    int lane = tid & 31;
    int h    = half * 4 + w;

    float scale = __expf(fminf(ls[h], 4.60517018598809f));   // log(100)

    if (lane < VTOK) {
        float* kr = sq + lane * SQ_STRIDE + 128 + w * 32;
        float kv[32];
        float ss = 0.0f;
        #pragma unroll
        for (int c = 0; c < 8; c++) {
            float4 t4 = *(const float4*)(kr + c * 4);
            kv[c*4+0] = t4.x; kv[c*4+1] = t4.y; kv[c*4+2] = t4.z; kv[c*4+3] = t4.w;
            ss += t4.x*t4.x + t4.y*t4.y + t4.z*t4.z + t4.w*t4.w;
        }
        float inv = 1.0f / fmaxf(sqrtf(ss), 1e-12f);
        #pragma unroll
        for (int c = 0; c < 8; c++) {
            float4 t4;
            t4.x = kv[c*4+0]*inv; t4.y = kv[c*4+1]*inv;
            t4.z = kv[c*4+2]*inv; t4.w = kv[c*4+3]*inv;
            *(float4*)(kr + c * 4) = t4;
        }
    }
    __syncwarp();

    int i = lane < VTOK ? lane : 0;
    const float* qr = sq + i * SQ_STRIDE + w * 32;
    float q[32];
    float ss = 0.0f;
    #pragma unroll
    for (int c = 0; c < 8; c++) {
        float4 t4 = *(const float4*)(qr + c * 4);
        q[c*4+0] = t4.x; q[c*4+1] = t4.y; q[c*4+2] = t4.z; q[c*4+3] = t4.w;
        ss += t4.x*t4.x + t4.y*t4.y + t4.z*t4.z + t4.w*t4.w;
    }
    float qf = scale / (5.65685424949238f * fmaxf(sqrtf(ss), 1e-12f));
    #pragma unroll
    for (int d = 0; d < 32; d++) q[d] *= qf;

    float p[VTOK];
    #pragma unroll
    for (int j = 0; j < VTOK; j++) {
        const float* kr = sq + j * SQ_STRIDE + 128 + w * 32;
        float a = 0.0f;
        #pragma unroll
        for (int c = 0; c < 8; c++) {
            float4 k4 = *(const float4*)(kr + c * 4);
            a += q[c*4+0]*k4.x + q[c*4+1]*k4.y + q[c*4+2]*k4.z + q[c*4+3]*k4.w;
        }
        p[j] = a;
    }

    float m = p[0];
    #pragma unroll
    for (int j = 1; j < VTOK; j++) m = fmaxf(m, p[j]);
    float s = 0.0f;
    #pragma unroll
    for (int j = 0; j < VTOK; j++) { p[j] = __expf(p[j] - m); s += p[j]; }
    float invs = 1.0f / s;

    float o[32];
    #pragma unroll
    for (int d = 0; d < 32; d++) o[d] = 0.0f;
    #pragma unroll
    for (int j = 0; j < VTOK; j++) {
        const float* vr = sq + j * SQ_STRIDE + 256 + w * 32;
        float pj = p[j] * invs;
        #pragma unroll
        for (int c = 0; c < 8; c++) {
            float4 v4 = *(const float4*)(vr + c * 4);
            o[c*4+0] += pj * v4.x; o[c*4+1] += pj * v4.y;
            o[c*4+2] += pj * v4.z; o[c*4+3] += pj * v4.w;
        }
    }

    if (lane < VTOK) {
        float* dst = ao + ((size_t)g * VTOK + lane) * 256 + h * 32;
        #pragma unroll
        for (int c = 0; c < 8; c++) {
            float4 t4;
            t4.x = tf32r(o[c*4+0]); t4.y = tf32r(o[c*4+1]);
            t4.z = tf32r(o[c*4+2]); t4.w = tf32r(o[c*4+3]);
            *(float4*)(dst + c * 4) = t4;
        }
    }
}

// ---------------------------------------------------------------------------
// Launch
// ---------------------------------------------------------------------------
extern "C" void kernel_launch(void* const* d_in, const int* in_sizes, int n_in,
                              void* d_out, int out_size)
{
    const float* x       = (const float*)d_in[0];
    const float* ln1_g   = (const float*)d_in[1];
    const float* ln1_b   = (const float*)d_in[2];
    const float* qkv_w   = (const float*)d_in[3];
    const float* qkv_b   = (const float*)d_in[4];
    const float* proj_w  = (const float*)d_in[5];
    const float* proj_b  = (const float*)d_in[6];
    const float* lscale  = (const float*)d_in[7];
    const float* ln2_g   = (const float*)d_in[8];
    const float* ln2_b   = (const float*)d_in[9];
    const float* ffn_w1  = (const float*)d_in[10];
    const float* ffn_b1  = (const float*)d_in[11];
    const float* ffn_w2  = (const float*)d_in[12];
    const float* ffn_b2  = (const float*)d_in[13];

    float *y, *qkv, *ao, *xf, *y2, *h, *wbuf;
    cudaGetSymbolAddress((void**)&y,    g_y);
    cudaGetSymbolAddress((void**)&qkv,  g_qkv);
    cudaGetSymbolAddress((void**)&ao,   g_ao);
    cudaGetSymbolAddress((void**)&xf,   g_xf);
    cudaGetSymbolAddress((void**)&y2,   g_y2);
    cudaGetSymbolAddress((void**)&h,    g_h);
    cudaGetSymbolAddress((void**)&wbuf, g_w);

    // 0) pre-round weights to tf32 (rna)
    round_w_kernel<<<(256*768/4 + 255)/256, 256>>>(qkv_w,  wbuf + W_QKV,  256*768/4);
    round_w_kernel<<<(256*256/4 + 255)/256, 256>>>(proj_w, wbuf + W_PROJ, 256*256/4);
    round_w_kernel<<<(256*1024/4 + 255)/256, 256>>>(ffn_w1, wbuf + W_FFN1, 256*1024/4);
    round_w_kernel<<<(1024*256/4 + 255)/256, 256>>>(ffn_w2, wbuf + W_FFN2, 1024*256/4);

    // 1) LN1 (tf32-rounded output)
    ln_kernel<<<NTOK / 8, 256>>>(x, ln1_g, ln1_b, y);
    // 2) QKV = y @ Wqkv + b
    gemm_tf32<1><<<dim3(6, NTOK / 128), 256>>>(y, wbuf + W_QKV, qkv_b, nullptr, qkv, 768, 256);
    // 3) cosine attention (tf32-rounded output)
    attn_kernel<<<NGRP * 2, 128>>>(qkv, lscale, ao);
    // 4) xf = ao @ Wproj + b + x
    gemm_tf32<3><<<dim3(2, NTOK / 128), 256>>>(ao, wbuf + W_PROJ, proj_b, x, xf, 256, 256);
    // 5) LN2 (tf32-rounded output)
    ln_kernel<<<NTOK / 8, 256>>>(xf, ln2_g, ln2_b, y2);
    // 6) h = gelu(y2 @ W1 + b1)  (tf32-rounded output)
    gemm_tf32<2><<<dim3(8, NTOK / 128), 256>>>(y2, wbuf + W_FFN1, ffn_b1, nullptr, h, 1024, 256);
    // 7) out = h @ W2 + b2 + xf
    gemm_tf32<3><<<dim3(2, NTOK / 128), 256>>>(h, wbuf + W_FFN2, ffn_b2, xf, (float*)d_out, 256, 1024);
}

// round 9
// speedup vs baseline: 1.4466x; 1.3145x over previous
#include <cuda_runtime.h>
#include <cuda_fp16.h>
#include <cstdint>

// ---------------------------------------------------------------------------
// Problem constants
// ---------------------------------------------------------------------------
#define NTOK   204800          // B*T*V = 64*128*25
#define NGRP   8192            // B*T
#define VTOK   25

// ---------------------------------------------------------------------------
// Device scratch (static; no allocation allowed)
// ---------------------------------------------------------------------------
__device__ __half g_y  [(size_t)NTOK * 256];     // LN1 out (GEMM A)
__device__ float  g_qkv[(size_t)NTOK * 768];     // QKV out (attention in, fp32)
__device__ __half g_ao [(size_t)NTOK * 256];     // attention out (GEMM A)
__device__ float  g_xf [(size_t)NTOK * 256];     // residual stream (fp32)
__device__ __half g_y2 [(size_t)NTOK * 256];     // LN2 out (GEMM A)
__device__ __half g_h  [(size_t)NTOK * 1024];    // GELU out (GEMM A)
// transposed + fp16-rounded weights, stored [N][K] K-major
#define W_QKV  0
#define W_PROJ (256 * 768)
#define W_FFN1 (W_PROJ + 256 * 256)
#define W_FFN2 (W_FFN1 + 256 * 1024)
#define W_TOT  (W_FFN2 + 1024 * 256)
__device__ __half g_w[(size_t)W_TOT];

// ---------------------------------------------------------------------------
// Helpers
// ---------------------------------------------------------------------------
__device__ __forceinline__ float gelu_exact(float x) {
    return 0.5f * x * (1.0f + erff(x * 0.70710678118654752f));
}

__device__ __forceinline__ void cp16(unsigned dst, const void* src) {
    asm volatile("cp.async.cg.shared.global [%0], [%1], 16;" :: "r"(dst), "l"(src));
}
#define CP_COMMIT() asm volatile("cp.async.commit_group;")
#define CP_WAIT1()  asm volatile("cp.async.wait_group 1;" ::: "memory")

// fp16 MMA m16n8k16: D(f32) += A(f16) x B(f16)
__device__ __forceinline__ void mma_f16(float* d, const unsigned* a, const unsigned* b) {
    asm volatile(
        "mma.sync.aligned.m16n8k16.row.col.f32.f16.f16.f32 "
        "{%0,%1,%2,%3}, {%4,%5,%6,%7}, {%8,%9}, {%0,%1,%2,%3};"
        : "+f"(d[0]), "+f"(d[1]), "+f"(d[2]), "+f"(d[3])
        : "r"(a[0]), "r"(a[1]), "r"(a[2]), "r"(a[3]), "r"(b[0]), "r"(b[1]));
}

// ---------------------------------------------------------------------------
// Weight transpose + fp16 rounding: dst[n*K + k] = half(src[k*N + n])
// ---------------------------------------------------------------------------
__global__ __launch_bounds__(256)
void transpose_round(const float* __restrict__ src, __half* __restrict__ dst,
                     int K, int N)
{
    __shared__ float t[32][33];
    int n0 = blockIdx.x * 32, k0 = blockIdx.y * 32;
    int tx = threadIdx.x & 31, ty = threadIdx.x >> 5;   // 32 x 8
    #pragma unroll
    for (int i = 0; i < 4; i++)
        t[ty + i * 8][tx] = src[(long)(k0 + ty + i * 8) * N + n0 + tx];
    __syncthreads();
    #pragma unroll
    for (int i = 0; i < 4; i++)
        dst[(long)(n0 + ty + i * 8) * K + k0 + tx] = __float2half_rn(t[tx][ty + i * 8]);
}

// ---------------------------------------------------------------------------
// LayerNorm: one warp per row of 256. Output fp16 (GEMM A operand).
// ---------------------------------------------------------------------------
__global__ __launch_bounds__(256)
void ln_kernel(const float* __restrict__ x, const float* __restrict__ g,
               const float* __restrict__ b, __half* __restrict__ y)
{
    int row  = blockIdx.x * 8 + (threadIdx.x >> 5);
    int lane = threadIdx.x & 31;
    const float* xr = x + (size_t)row * 256;

    float4 v0 = *(const float4*)(xr + lane * 4);
    float4 v1 = *(const float4*)(xr + 128 + lane * 4);

    float s = v0.x + v0.y + v0.z + v0.w + v1.x + v1.y + v1.z + v1.w;
    #pragma unroll
    for (int o = 16; o; o >>= 1) s += __shfl_xor_sync(0xFFFFFFFFu, s, o);
    float mean = s * (1.0f / 256.0f);

    float d0 = v0.x - mean, d1 = v0.y - mean, d2 = v0.z - mean, d3 = v0.w - mean;
    float d4 = v1.x - mean, d5 = v1.y - mean, d6 = v1.z - mean, d7 = v1.w - mean;
    float vs = d0*d0 + d1*d1 + d2*d2 + d3*d3 + d4*d4 + d5*d5 + d6*d6 + d7*d7;
    #pragma unroll
    for (int o = 16; o; o >>= 1) vs += __shfl_xor_sync(0xFFFFFFFFu, vs, o);
    float rstd = rsqrtf(vs * (1.0f / 256.0f) + 1e-5f);

    float4 g0 = *(const float4*)(g + lane * 4);
    float4 g1 = *(const float4*)(g + 128 + lane * 4);
    float4 b0 = *(const float4*)(b + lane * 4);
    float4 b1 = *(const float4*)(b + 128 + lane * 4);

    __half2* yr = (__half2*)(y + (size_t)row * 256);
    yr[lane * 2]          = __floats2half2_rn(d0 * rstd * g0.x + b0.x, d1 * rstd * g0.y + b0.y);
    yr[lane * 2 + 1]      = __floats2half2_rn(d2 * rstd * g0.z + b0.z, d3 * rstd * g0.w + b0.w);
    yr[64 + lane * 2]     = __floats2half2_rn(d4 * rstd * g1.x + b1.x, d5 * rstd * g1.y + b1.y);
    yr[64 + lane * 2 + 1] = __floats2half2_rn(d6 * rstd * g1.z + b1.z, d7 * rstd * g1.w + b1.w);
}

// ---------------------------------------------------------------------------
// fp16 tensor GEMM: C[M,N] = A[M,K](f16) @ Wt[N,K](f16)^T + epilogue (fp32 acc)
//   EPI 1: +bias -> fp32 C | EPI 2: +bias, GELU -> fp16 C | EPI 3: +bias+resid -> fp32 C
// CTA 128x128, 8 warps (2x4) of 64x32, mma m16n8k16, K-chunk 16.
// 3-stage cp.async pipeline; smem pitch 12 words (conflict-free frag reads).
// ---------------------------------------------------------------------------
#define PITCH  12               // 32-bit words per tile row (8 data + 4 pad)
#define TILE_W (128 * PITCH)    // 1536 words per tile

template<int EPI>
__global__ __launch_bounds__(256, 2)
void gemm_f16(const __half* __restrict__ A, const __half* __restrict__ W,
              const float* __restrict__ bias, const float* __restrict__ resid,
              void* __restrict__ Cv, int N, int K)
{
    __shared__ unsigned sm[3][2][TILE_W];   // [stage][A|B][...]  36.9 KB

    int tid  = threadIdx.x;
    int w    = tid >> 5;
    int lane = tid & 31;
    int g    = lane >> 2;
    int t    = lane & 3;
    int wm   = w >> 2;      // 0..1
    int wn   = w & 3;       // 0..3

    long mBase = (long)blockIdx.y * 128;
    int  nBase = blockIdx.x * 128;

    const __half* Ab = A + mBase * (long)K;
    const __half* Wb = W + (long)nBase * K;
    unsigned smb = (unsigned)__cvta_generic_to_shared(sm);

    float acc[4][4][4];
    #pragma unroll
    for (int mt = 0; mt < 4; mt++)
        #pragma unroll
        for (int nt = 0; nt < 4; nt++)
            #pragma unroll
            for (int c = 0; c < 4; c++) acc[mt][nt][c] = 0.0f;

    int TC = K >> 4;                 // number of K=16 chunks

    // per-thread cp.async assignment: 256 threads, 1 A-chunk + 1 B-chunk each
    int  lr   = tid >> 1, hh = tid & 1;       // row 0..127, half-of-row 0..1
    long goff = (long)lr * K + hh * 8;        // gmem offset (halves)
    unsigned soff = (unsigned)((lr * PITCH + hh * 4) * 4);   // smem byte offset

    #define LOAD(c)                                                        \
    {                                                                      \
        unsigned st = smb + (unsigned)((c) % 3) * (2u * TILE_W * 4u);      \
        cp16(st + soff, Ab + (c) * 16 + goff);                             \
        cp16(st + TILE_W * 4u + soff, Wb + (c) * 16 + goff);               \
    }

    LOAD(0); CP_COMMIT();
    LOAD(1); CP_COMMIT();

    for (int c = 0; c < TC; c++) {
        CP_WAIT1();
        __syncthreads();

        const unsigned* sa = sm[c % 3][0];
        const unsigned* sb = sm[c % 3][1];

        unsigned af[4][4];
        #pragma unroll
        for (int mt = 0; mt < 4; mt++) {
            int mr = wm * 64 + mt * 16 + g;
            af[mt][0] = sa[mr * PITCH + t];
            af[mt][1] = sa[(mr + 8) * PITCH + t];
            af[mt][2] = sa[mr * PITCH + t + 4];
            af[mt][3] = sa[(mr + 8) * PITCH + t + 4];
        }
        unsigned bf[4][2];
        #pragma unroll
        for (int nt = 0; nt < 4; nt++) {
            int nr = wn * 32 + nt * 8 + g;
            bf[nt][0] = sb[nr * PITCH + t];
            bf[nt][1] = sb[nr * PITCH + t + 4];
        }
        #pragma unroll
        for (int mt = 0; mt < 4; mt++)
            #pragma unroll
            for (int nt = 0; nt < 4; nt++)
                mma_f16(acc[mt][nt], af[mt], bf[nt]);

        if (c + 2 < TC) LOAD(c + 2);
        CP_COMMIT();
    }
    #undef LOAD

    // ---- epilogue ----
    #pragma unroll
    for (int mt = 0; mt < 4; mt++) {
        long r0 = mBase + wm * 64 + mt * 16 + g;
        long r1 = r0 + 8;
        #pragma unroll
        for (int nt = 0; nt < 4; nt++) {
            int cb = nBase + wn * 32 + nt * 8 + t * 2;
            float bb0 = bias[cb], bb1 = bias[cb + 1];
            float c0 = acc[mt][nt][0] + bb0;
            float c1 = acc[mt][nt][1] + bb1;
            float c2 = acc[mt][nt][2] + bb0;
            float c3 = acc[mt][nt][3] + bb1;
            if (EPI == 2) {          // GELU -> fp16 output
                __half* C = (__half*)Cv;
                *(__half2*)(C + r0 * N + cb) =
                    __floats2half2_rn(gelu_exact(c0), gelu_exact(c1));
                *(__half2*)(C + r1 * N + cb) =
                    __floats2half2_rn(gelu_exact(c2), gelu_exact(c3));
            } else {
                float* C = (float*)Cv;
                if (EPI == 3) {
                    float2 ra = *(const float2*)(resid + r0 * N + cb);
                    float2 rb = *(const float2*)(resid + r1 * N + cb);
                    c0 += ra.x; c1 += ra.y; c2 += rb.x; c3 += rb.y;
                }
                float2 o0; o0.x = c0; o0.y = c1;
                float2 o1; o1.x = c2; o1.y = c3;
                *(float2*)(C + r0 * N + cb) = o0;
                *(float2*)(C + r1 * N + cb) = o1;
            }
        }
    }
}

// ---------------------------------------------------------------------------
// Cosine attention. One block = (group, half); 4 warps = 4 heads.
// Reads fp32 qkv; writes fp16 ao (proj GEMM A operand).
// ---------------------------------------------------------------------------
#define SQ_STRIDE 388

__global__ __launch_bounds__(128)
void attn_kernel(const float* __restrict__ qkv, const float* __restrict__ ls,
                 __half* __restrict__ ao)
{
    __shared__ float sq[VTOK * SQ_STRIDE];

    int g    = blockIdx.x >> 1;
    int half = blockIdx.x & 1;
    int tid  = threadIdx.x;

    const float* src = qkv + (size_t)g * VTOK * 768 + half * 128;
    for (int idx = tid; idx < VTOK * 96; idx += 128) {
        int r = idx / 96, rem = idx % 96;
        int s = rem >> 5, c4 = rem & 31;
        float4 v = *(const float4*)(src + (size_t)r * 768 + s * 256 + c4 * 4);
        *(float4*)(sq + r * SQ_STRIDE + s * 128 + c4 * 4) = v;
    }
    __syncthreads();

    int w    = tid >> 5;
    int lane = tid & 31;
    int h    = half * 4 + w;

    float scale = __expf(fminf(ls[h], 4.60517018598809f));   // log(100)

    if (lane < VTOK) {
        float* kr = sq + lane * SQ_STRIDE + 128 + w * 32;
        float kv[32];
        float ss = 0.0f;
        #pragma unroll
        for (int c = 0; c < 8; c++) {
            float4 t4 = *(const float4*)(kr + c * 4);
            kv[c*4+0] = t4.x; kv[c*4+1] = t4.y; kv[c*4+2] = t4.z; kv[c*4+3] = t4.w;
            ss += t4.x*t4.x + t4.y*t4.y + t4.z*t4.z + t4.w*t4.w;
        }
        float inv = 1.0f / fmaxf(sqrtf(ss), 1e-12f);
        #pragma unroll
        for (int c = 0; c < 8; c++) {
            float4 t4;
            t4.x = kv[c*4+0]*inv; t4.y = kv[c*4+1]*inv;
            t4.z = kv[c*4+2]*inv; t4.w = kv[c*4+3]*inv;
            *(float4*)(kr + c * 4) = t4;
        }
    }
    __syncwarp();

    int i = lane < VTOK ? lane : 0;
    const float* qr = sq + i * SQ_STRIDE + w * 32;
    float q[32];
    float ss = 0.0f;
    #pragma unroll
    for (int c = 0; c < 8; c++) {
        float4 t4 = *(const float4*)(qr + c * 4);
        q[c*4+0] = t4.x; q[c*4+1] = t4.y; q[c*4+2] = t4.z; q[c*4+3] = t4.w;
        ss += t4.x*t4.x + t4.y*t4.y + t4.z*t4.z + t4.w*t4.w;
    }
    float qf = scale / (5.65685424949238f * fmaxf(sqrtf(ss), 1e-12f));
    #pragma unroll
    for (int d = 0; d < 32; d++) q[d] *= qf;

    float p[VTOK];
    #pragma unroll
    for (int j = 0; j < VTOK; j++) {
        const float* kr = sq + j * SQ_STRIDE + 128 + w * 32;
        float a = 0.0f;
        #pragma unroll
        for (int c = 0; c < 8; c++) {
            float4 k4 = *(const float4*)(kr + c * 4);
            a += q[c*4+0]*k4.x + q[c*4+1]*k4.y + q[c*4+2]*k4.z + q[c*4+3]*k4.w;
        }
        p[j] = a;
    }

    float m = p[0];
    #pragma unroll
    for (int j = 1; j < VTOK; j++) m = fmaxf(m, p[j]);
    float s = 0.0f;
    #pragma unroll
    for (int j = 0; j < VTOK; j++) { p[j] = __expf(p[j] - m); s += p[j]; }
    float invs = 1.0f / s;

    float o[32];
    #pragma unroll
    for (int d = 0; d < 32; d++) o[d] = 0.0f;
    #pragma unroll
    for (int j = 0; j < VTOK; j++) {
        const float* vr = sq + j * SQ_STRIDE + 256 + w * 32;
        float pj = p[j] * invs;
        #pragma unroll
        for (int c = 0; c < 8; c++) {
            float4 v4 = *(const float4*)(vr + c * 4);
            o[c*4+0] += pj * v4.x; o[c*4+1] += pj * v4.y;
            o[c*4+2] += pj * v4.z; o[c*4+3] += pj * v4.w;
        }
    }

    if (lane < VTOK) {
        __half2* dst = (__half2*)(ao + ((size_t)g * VTOK + lane) * 256 + h * 32);
        #pragma unroll
        for (int c = 0; c < 8; c++) {
            dst[c * 2]     = __floats2half2_rn(o[c*4+0], o[c*4+1]);
            dst[c * 2 + 1] = __floats2half2_rn(o[c*4+2], o[c*4+3]);
        }
    }
}

// ---------------------------------------------------------------------------
// Launch
// ---------------------------------------------------------------------------
extern "C" void kernel_launch(void* const* d_in, const int* in_sizes, int n_in,
                              void* d_out, int out_size)
{
    const float* x       = (const float*)d_in[0];
    const float* ln1_g   = (const float*)d_in[1];
    const float* ln1_b   = (const float*)d_in[2];
    const float* qkv_w   = (const float*)d_in[3];
    const float* qkv_b   = (const float*)d_in[4];
    const float* proj_w  = (const float*)d_in[5];
    const float* proj_b  = (const float*)d_in[6];
    const float* lscale  = (const float*)d_in[7];
    const float* ln2_g   = (const float*)d_in[8];
    const float* ln2_b   = (const float*)d_in[9];
    const float* ffn_w1  = (const float*)d_in[10];
    const float* ffn_b1  = (const float*)d_in[11];
    const float* ffn_w2  = (const float*)d_in[12];
    const float* ffn_b2  = (const float*)d_in[13];

    __half *y, *ao, *y2, *h, *wbuf;
    float  *qkv, *xf;
    cudaGetSymbolAddress((void**)&y,    g_y);
    cudaGetSymbolAddress((void**)&qkv,  g_qkv);
    cudaGetSymbolAddress((void**)&ao,   g_ao);
    cudaGetSymbolAddress((void**)&xf,   g_xf);
    cudaGetSymbolAddress((void**)&y2,   g_y2);
    cudaGetSymbolAddress((void**)&h,    g_h);
    cudaGetSymbolAddress((void**)&wbuf, g_w);

    // 0) weights -> transposed [N][K] fp16
    transpose_round<<<dim3(768 / 32, 256 / 32), 256>>>(qkv_w,  wbuf + W_QKV,  256, 768);
    transpose_round<<<dim3(256 / 32, 256 / 32), 256>>>(proj_w, wbuf + W_PROJ, 256, 256);
    transpose_round<<<dim3(1024 / 32, 256 / 32), 256>>>(ffn_w1, wbuf + W_FFN1, 256, 1024);
    transpose_round<<<dim3(256 / 32, 1024 / 32), 256>>>(ffn_w2, wbuf + W_FFN2, 1024, 256);

    // 1) LN1 -> fp16 y
    ln_kernel<<<NTOK / 8, 256>>>(x, ln1_g, ln1_b, y);
    // 2) QKV = y @ Wqkv + b  -> fp32 qkv
    gemm_f16<1><<<dim3(6, NTOK / 128), 256>>>(y, wbuf + W_QKV, qkv_b, nullptr, qkv, 768, 256);
    // 3) cosine attention -> fp16 ao
    attn_kernel<<<NGRP * 2, 128>>>(qkv, lscale, ao);
    // 4) xf = ao @ Wproj + b + x  -> fp32
    gemm_f16<3><<<dim3(2, NTOK / 128), 256>>>(ao, wbuf + W_PROJ, proj_b, x, xf, 256, 256);
    // 5) LN2 -> fp16 y2
    ln_kernel<<<NTOK / 8, 256>>>(xf, ln2_g, ln2_b, y2);
    // 6) h = gelu(y2 @ W1 + b1) -> fp16
    gemm_f16<2><<<dim3(8, NTOK / 128), 256>>>(y2, wbuf + W_FFN1, ffn_b1, nullptr, h, 1024, 256);
    // 7) out = h @ W2 + b2 + xf -> fp32 d_out
    gemm_f16<3><<<dim3(2, NTOK / 128), 256>>>(h, wbuf + W_FFN2, ffn_b2, xf, (float*)d_out, 256, 1024);
}

// round 10
// speedup vs baseline: 1.5503x; 1.0717x over previous
#include <cuda_runtime.h>
#include <cuda_fp16.h>
#include <cstdint>

// ---------------------------------------------------------------------------
// Problem constants
// ---------------------------------------------------------------------------
#define NTOK   204800          // B*T*V = 64*128*25
#define NGRP   8192            // B*T
#define VTOK   25

// ---------------------------------------------------------------------------
// Device scratch (static; no allocation allowed)
// ---------------------------------------------------------------------------
__device__ __half g_y  [(size_t)NTOK * 256];     // LN1 out (GEMM A)
__device__ __half g_qkv[(size_t)NTOK * 768];     // QKV out (fp16 now)
__device__ __half g_ao [(size_t)NTOK * 256];     // attention out (GEMM A)
__device__ float  g_xf [(size_t)NTOK * 256];     // residual stream (fp32)
__device__ __half g_y2 [(size_t)NTOK * 256];     // LN2 out (GEMM A)
__device__ __half g_h  [(size_t)NTOK * 1024];    // GELU out (GEMM A)
// transposed + fp16-rounded weights, stored [N][K] K-major
#define W_QKV  0
#define W_PROJ (256 * 768)
#define W_FFN1 (W_PROJ + 256 * 256)
#define W_FFN2 (W_FFN1 + 256 * 1024)
#define W_TOT  (W_FFN2 + 1024 * 256)
__device__ __half g_w[(size_t)W_TOT];

// ---------------------------------------------------------------------------
// Helpers
// ---------------------------------------------------------------------------
__device__ __forceinline__ float gelu_exact(float x) {
    return 0.5f * x * (1.0f + erff(x * 0.70710678118654752f));
}

__device__ __forceinline__ void cp16(unsigned dst, const void* src) {
    asm volatile("cp.async.cg.shared.global [%0], [%1], 16;" :: "r"(dst), "l"(src));
}
#define CP_COMMIT() asm volatile("cp.async.commit_group;")
#define CP_WAIT1()  asm volatile("cp.async.wait_group 1;" ::: "memory")

// fp16 MMA m16n8k16: D(f32) += A(f16) x B(f16)
__device__ __forceinline__ void mma_f16(float* d, const unsigned* a, const unsigned* b) {
    asm volatile(
        "mma.sync.aligned.m16n8k16.row.col.f32.f16.f16.f32 "
        "{%0,%1,%2,%3}, {%4,%5,%6,%7}, {%8,%9}, {%0,%1,%2,%3};"
        : "+f"(d[0]), "+f"(d[1]), "+f"(d[2]), "+f"(d[3])
        : "r"(a[0]), "r"(a[1]), "r"(a[2]), "r"(a[3]), "r"(b[0]), "r"(b[1]));
}

__device__ __forceinline__ void ldsm_x4(unsigned* r, unsigned addr) {
    asm volatile("ldmatrix.sync.aligned.m8n8.x4.shared.b16 {%0,%1,%2,%3}, [%4];"
                 : "=r"(r[0]), "=r"(r[1]), "=r"(r[2]), "=r"(r[3]) : "r"(addr));
}

// ---------------------------------------------------------------------------
// Weight transpose + fp16 rounding: dst[n*K + k] = half(src[k*N + n])
// ---------------------------------------------------------------------------
__global__ __launch_bounds__(256)
void transpose_round(const float* __restrict__ src, __half* __restrict__ dst,
                     int K, int N)
{
    __shared__ float t[32][33];
    int n0 = blockIdx.x * 32, k0 = blockIdx.y * 32;
    int tx = threadIdx.x & 31, ty = threadIdx.x >> 5;   // 32 x 8
    #pragma unroll
    for (int i = 0; i < 4; i++)
        t[ty + i * 8][tx] = src[(long)(k0 + ty + i * 8) * N + n0 + tx];
    __syncthreads();
    #pragma unroll
    for (int i = 0; i < 4; i++)
        dst[(long)(n0 + ty + i * 8) * K + k0 + tx] = __float2half_rn(t[tx][ty + i * 8]);
}

// ---------------------------------------------------------------------------
// LayerNorm: one warp per row of 256. Output fp16 (GEMM A operand).
// ---------------------------------------------------------------------------
__global__ __launch_bounds__(256)
void ln_kernel(const float* __restrict__ x, const float* __restrict__ g,
               const float* __restrict__ b, __half* __restrict__ y)
{
    int row  = blockIdx.x * 8 + (threadIdx.x >> 5);
    int lane = threadIdx.x & 31;
    const float* xr = x + (size_t)row * 256;

    float4 v0 = *(const float4*)(xr + lane * 4);
    float4 v1 = *(const float4*)(xr + 128 + lane * 4);

    float s = v0.x + v0.y + v0.z + v0.w + v1.x + v1.y + v1.z + v1.w;
    #pragma unroll
    for (int o = 16; o; o >>= 1) s += __shfl_xor_sync(0xFFFFFFFFu, s, o);
    float mean = s * (1.0f / 256.0f);

    float d0 = v0.x - mean, d1 = v0.y - mean, d2 = v0.z - mean, d3 = v0.w - mean;
    float d4 = v1.x - mean, d5 = v1.y - mean, d6 = v1.z - mean, d7 = v1.w - mean;
    float vs = d0*d0 + d1*d1 + d2*d2 + d3*d3 + d4*d4 + d5*d5 + d6*d6 + d7*d7;
    #pragma unroll
    for (int o = 16; o; o >>= 1) vs += __shfl_xor_sync(0xFFFFFFFFu, vs, o);
    float rstd = rsqrtf(vs * (1.0f / 256.0f) + 1e-5f);

    float4 g0 = *(const float4*)(g + lane * 4);
    float4 g1 = *(const float4*)(g + 128 + lane * 4);
    float4 b0 = *(const float4*)(b + lane * 4);
    float4 b1 = *(const float4*)(b + 128 + lane * 4);

    __half2* yr = (__half2*)(y + (size_t)row * 256);
    yr[lane * 2]          = __floats2half2_rn(d0 * rstd * g0.x + b0.x, d1 * rstd * g0.y + b0.y);
    yr[lane * 2 + 1]      = __floats2half2_rn(d2 * rstd * g0.z + b0.z, d3 * rstd * g0.w + b0.w);
    yr[64 + lane * 2]     = __floats2half2_rn(d4 * rstd * g1.x + b1.x, d5 * rstd * g1.y + b1.y);
    yr[64 + lane * 2 + 1] = __floats2half2_rn(d6 * rstd * g1.z + b1.z, d7 * rstd * g1.w + b1.w);
}

// ---------------------------------------------------------------------------
// fp16 tensor GEMM v2: C[M,N] = A[M,K](f16) @ Wt[N,K](f16)^T + epilogue
//   EPI 1: +bias -> fp16 C | EPI 2: +bias, GELU -> fp16 C
//   EPI 3: +bias+resid -> fp32 C
// CTA 128x128, 4 warps (2x2) of 64x64, mma m16n8k16 via ldmatrix.x4.
// K-chunk 16, 3-stage cp.async pipeline, pitch 12 words (conflict-free).
// ---------------------------------------------------------------------------
#define PITCH  12               // 32-bit words per tile row (8 data + 4 pad)
#define TILE_W (128 * PITCH)    // words per tile
#define ST_W   (2 * TILE_W)     // words per stage (A+B)

template<int EPI>
__global__ __launch_bounds__(128, 2)
void gemm_f16(const __half* __restrict__ A, const __half* __restrict__ W,
              const float* __restrict__ bias, const float* __restrict__ resid,
              void* __restrict__ Cv, int N, int K)
{
    __shared__ unsigned sm[3 * ST_W];   // 36 KB

    int tid  = threadIdx.x;
    int w    = tid >> 5;
    int lane = tid & 31;
    int g    = lane >> 2;
    int t    = lane & 3;
    int wm   = w >> 1;      // 0..1
    int wn   = w & 1;       // 0..1

    long mBase = (long)blockIdx.y * 128;
    int  nBase = blockIdx.x * 128;

    const __half* Ab = A + mBase * (long)K;
    const __half* Wb = W + (long)nBase * K;
    unsigned smb = (unsigned)__cvta_generic_to_shared(sm);

    float acc[4][8][4];
    #pragma unroll
    for (int mt = 0; mt < 4; mt++)
        #pragma unroll
        for (int nt = 0; nt < 8; nt++)
            #pragma unroll
            for (int c = 0; c < 4; c++) acc[mt][nt][c] = 0.0f;

    int TC = K >> 4;

    // cp.async: per thread 2 A rows + 2 B rows, 16B each.
    // threads (2 per row): rows r=tid>>1 and 64+(tid>>1); 16B-half hh=tid&1.
    int rr = tid >> 1, hh = tid & 1;
    unsigned sA0 = (unsigned)((rr * PITCH + hh * 4) * 4);
    unsigned sA1 = (unsigned)(((rr + 64) * PITCH + hh * 4) * 4);
    long gA0 = (long)rr * K + hh * 8;
    long gA1 = (long)(rr + 64) * K + hh * 8;

    #define LOAD(c)                                                        \
    {                                                                      \
        unsigned st = smb + (unsigned)((c) % 3) * (ST_W * 4u);             \
        const __half* ap = Ab + (c) * 16;                                  \
        const __half* bp = Wb + (c) * 16;                                  \
        cp16(st + sA0, ap + gA0);                                          \
        cp16(st + sA1, ap + gA1);                                          \
        cp16(st + TILE_W * 4u + sA0, bp + gA0);                            \
        cp16(st + TILE_W * 4u + sA1, bp + gA1);                            \
    }

    LOAD(0); CP_COMMIT();
    LOAD(1); CP_COMMIT();

    // ldmatrix lane addressing
    int rowA  = (lane & 7) + ((lane >> 3) & 1) * 8;   // m within 16-row tile
    int halfA = lane >> 4;                            // k half (0/1)
    int rowB  = (lane & 7) + (lane >> 4) * 8;         // n within 16-row pair
    int halfB = (lane >> 3) & 1;                      // k half

    for (int c = 0; c < TC; c++) {
        CP_WAIT1();
        __syncthreads();

        unsigned sa = smb + (unsigned)(c % 3) * (ST_W * 4u);
        unsigned sb = sa + TILE_W * 4u;

        unsigned af[4][4];
        #pragma unroll
        for (int mt = 0; mt < 4; mt++)
            ldsm_x4(af[mt], sa + (unsigned)(((wm * 64 + mt * 16 + rowA) * PITCH + halfA * 4) * 4));

        unsigned bf[8][2];
        #pragma unroll
        for (int p = 0; p < 4; p++) {
            unsigned r[4];
            ldsm_x4(r, sb + (unsigned)(((wn * 64 + p * 16 + rowB) * PITCH + halfB * 4) * 4));
            bf[2*p][0] = r[0]; bf[2*p][1] = r[1];
            bf[2*p+1][0] = r[2]; bf[2*p+1][1] = r[3];
        }

        #pragma unroll
        for (int mt = 0; mt < 4; mt++)
            #pragma unroll
            for (int nt = 0; nt < 8; nt++)
                mma_f16(acc[mt][nt], af[mt], bf[nt]);

        if (c + 2 < TC) LOAD(c + 2);
        CP_COMMIT();
    }
    #undef LOAD

    // ---- epilogue ----
    #pragma unroll
    for (int mt = 0; mt < 4; mt++) {
        long r0 = mBase + wm * 64 + mt * 16 + g;
        long r1 = r0 + 8;
        #pragma unroll
        for (int nt = 0; nt < 8; nt++) {
            int cb = nBase + wn * 64 + nt * 8 + t * 2;
            float bb0 = bias[cb], bb1 = bias[cb + 1];
            float c0 = acc[mt][nt][0] + bb0;
            float c1 = acc[mt][nt][1] + bb1;
            float c2 = acc[mt][nt][2] + bb0;
            float c3 = acc[mt][nt][3] + bb1;
            if (EPI == 1) {          // -> fp16 output (qkv)
                __half* C = (__half*)Cv;
                *(__half2*)(C + r0 * N + cb) = __floats2half2_rn(c0, c1);
                *(__half2*)(C + r1 * N + cb) = __floats2half2_rn(c2, c3);
            } else if (EPI == 2) {   // GELU -> fp16 output
                __half* C = (__half*)Cv;
                *(__half2*)(C + r0 * N + cb) =
                    __floats2half2_rn(gelu_exact(c0), gelu_exact(c1));
                *(__half2*)(C + r1 * N + cb) =
                    __floats2half2_rn(gelu_exact(c2), gelu_exact(c3));
            } else {                 // +resid -> fp32 output
                float* C = (float*)Cv;
                float2 ra = *(const float2*)(resid + r0 * N + cb);
                float2 rb = *(const float2*)(resid + r1 * N + cb);
                float2 o0; o0.x = c0 + ra.x; o0.y = c1 + ra.y;
                float2 o1; o1.x = c2 + rb.x; o1.y = c3 + rb.y;
                *(float2*)(C + r0 * N + cb) = o0;
                *(float2*)(C + r1 * N + cb) = o1;
            }
        }
    }
}

// ---------------------------------------------------------------------------
// Cosine attention. One block = (group, half); 4 warps = 4 heads.
// Reads fp16 qkv (converted to fp32 in smem); writes fp16 ao.
// ---------------------------------------------------------------------------
#define SQ_STRIDE 388

__global__ __launch_bounds__(128)
void attn_kernel(const __half* __restrict__ qkv, const float* __restrict__ ls,
                 __half* __restrict__ ao)
{
    __shared__ float sq[VTOK * SQ_STRIDE];

    int g    = blockIdx.x >> 1;
    int half = blockIdx.x & 1;
    int tid  = threadIdx.x;

    // per token row: 3 sections (q/k/v) x 128 halves = 48 chunks of 8 halves
    const __half* src = qkv + (size_t)g * VTOK * 768 + half * 128;
    for (int idx = tid; idx < VTOK * 48; idx += 128) {
        int r = idx / 48, rem = idx % 48;
        int s = rem >> 4, c8 = rem & 15;
        const __half2* p = (const __half2*)(src + (size_t)r * 768 + s * 256 + c8 * 8);
        float* dst = sq + r * SQ_STRIDE + s * 128 + c8 * 8;
        #pragma unroll
        for (int u = 0; u < 4; u++) {
            float2 f = __half22float2(p[u]);
            dst[u * 2] = f.x; dst[u * 2 + 1] = f.y;
        }
    }
    __syncthreads();

    int w    = tid >> 5;
    int lane = tid & 31;
    int h    = half * 4 + w;

    float scale = __expf(fminf(ls[h], 4.60517018598809f));   // log(100)

    if (lane < VTOK) {
        float* kr = sq + lane * SQ_STRIDE + 128 + w * 32;
        float kv[32];
        float ss = 0.0f;
        #pragma unroll
        for (int c = 0; c < 8; c++) {
            float4 t4 = *(const float4*)(kr + c * 4);
            kv[c*4+0] = t4.x; kv[c*4+1] = t4.y; kv[c*4+2] = t4.z; kv[c*4+3] = t4.w;
            ss += t4.x*t4.x + t4.y*t4.y + t4.z*t4.z + t4.w*t4.w;
        }
        float inv = 1.0f / fmaxf(sqrtf(ss), 1e-12f);
        #pragma unroll
        for (int c = 0; c < 8; c++) {
            float4 t4;
            t4.x = kv[c*4+0]*inv; t4.y = kv[c*4+1]*inv;
            t4.z = kv[c*4+2]*inv; t4.w = kv[c*4+3]*inv;
            *(float4*)(kr + c * 4) = t4;
        }
    }
    __syncwarp();

    int i = lane < VTOK ? lane : 0;
    const float* qr = sq + i * SQ_STRIDE + w * 32;
    float q[32];
    float ss = 0.0f;
    #pragma unroll
    for (int c = 0; c < 8; c++) {
        float4 t4 = *(const float4*)(qr + c * 4);
        q[c*4+0] = t4.x; q[c*4+1] = t4.y; q[c*4+2] = t4.z; q[c*4+3] = t4.w;
        ss += t4.x*t4.x + t4.y*t4.y + t4.z*t4.z + t4.w*t4.w;
    }
    float qf = scale / (5.65685424949238f * fmaxf(sqrtf(ss), 1e-12f));
    #pragma unroll
    for (int d = 0; d < 32; d++) q[d] *= qf;

    float p[VTOK];
    #pragma unroll
    for (int j = 0; j < VTOK; j++) {
        const float* kr = sq + j * SQ_STRIDE + 128 + w * 32;
        float a = 0.0f;
        #pragma unroll
        for (int c = 0; c < 8; c++) {
            float4 k4 = *(const float4*)(kr + c * 4);
            a += q[c*4+0]*k4.x + q[c*4+1]*k4.y + q[c*4+2]*k4.z + q[c*4+3]*k4.w;
        }
        p[j] = a;
    }

    float m = p[0];
    #pragma unroll
    for (int j = 1; j < VTOK; j++) m = fmaxf(m, p[j]);
    float s = 0.0f;
    #pragma unroll
    for (int j = 0; j < VTOK; j++) { p[j] = __expf(p[j] - m); s += p[j]; }
    float invs = 1.0f / s;

    float o[32];
    #pragma unroll
    for (int d = 0; d < 32; d++) o[d] = 0.0f;
    #pragma unroll
    for (int j = 0; j < VTOK; j++) {
        const float* vr = sq + j * SQ_STRIDE + 256 + w * 32;
        float pj = p[j] * invs;
        #pragma unroll
        for (int c = 0; c < 8; c++) {
            float4 v4 = *(const float4*)(vr + c * 4);
            o[c*4+0] += pj * v4.x; o[c*4+1] += pj * v4.y;
            o[c*4+2] += pj * v4.z; o[c*4+3] += pj * v4.w;
        }
    }

    if (lane < VTOK) {
        __half2* dst = (__half2*)(ao + ((size_t)g * VTOK + lane) * 256 + h * 32);
        #pragma unroll
        for (int c = 0; c < 8; c++) {
            dst[c * 2]     = __floats2half2_rn(o[c*4+0], o[c*4+1]);
            dst[c * 2 + 1] = __floats2half2_rn(o[c*4+2], o[c*4+3]);
        }
    }
}

// ---------------------------------------------------------------------------
// Launch
// ---------------------------------------------------------------------------
extern "C" void kernel_launch(void* const* d_in, const int* in_sizes, int n_in,
                              void* d_out, int out_size)
{
    const float* x       = (const float*)d_in[0];
    const float* ln1_g   = (const float*)d_in[1];
    const float* ln1_b   = (const float*)d_in[2];
    const float* qkv_w   = (const float*)d_in[3];
    const float* qkv_b   = (const float*)d_in[4];
    const float* proj_w  = (const float*)d_in[5];
    const float* proj_b  = (const float*)d_in[6];
    const float* lscale  = (const float*)d_in[7];
    const float* ln2_g   = (const float*)d_in[8];
    const float* ln2_b   = (const float*)d_in[9];
    const float* ffn_w1  = (const float*)d_in[10];
    const float* ffn_b1  = (const float*)d_in[11];
    const float* ffn_w2  = (const float*)d_in[12];
    const float* ffn_b2  = (const float*)d_in[13];

    __half *y, *qkv, *ao, *y2, *h, *wbuf;
    float  *xf;
    cudaGetSymbolAddress((void**)&y,    g_y);
    cudaGetSymbolAddress((void**)&qkv,  g_qkv);
    cudaGetSymbolAddress((void**)&ao,   g_ao);
    cudaGetSymbolAddress((void**)&xf,   g_xf);
    cudaGetSymbolAddress((void**)&y2,   g_y2);
    cudaGetSymbolAddress((void**)&h,    g_h);
    cudaGetSymbolAddress((void**)&wbuf, g_w);

    // 0) weights -> transposed [N][K] fp16
    transpose_round<<<dim3(768 / 32, 256 / 32), 256>>>(qkv_w,  wbuf + W_QKV,  256, 768);
    transpose_round<<<dim3(256 / 32, 256 / 32), 256>>>(proj_w, wbuf + W_PROJ, 256, 256);
    transpose_round<<<dim3(1024 / 32, 256 / 32), 256>>>(ffn_w1, wbuf + W_FFN1, 256, 1024);
    transpose_round<<<dim3(256 / 32, 1024 / 32), 256>>>(ffn_w2, wbuf + W_FFN2, 1024, 256);

    // 1) LN1 -> fp16 y
    ln_kernel<<<NTOK / 8, 256>>>(x, ln1_g, ln1_b, y);
    // 2) QKV = y @ Wqkv + b  -> fp16 qkv
    gemm_f16<1><<<dim3(6, NTOK / 128), 128>>>(y, wbuf + W_QKV, qkv_b, nullptr, qkv, 768, 256);
    // 3) cosine attention -> fp16 ao
    attn_kernel<<<NGRP * 2, 128>>>(qkv, lscale, ao);
    // 4) xf = ao @ Wproj + b + x  -> fp32
    gemm_f16<3><<<dim3(2, NTOK / 128), 128>>>(ao, wbuf + W_PROJ, proj_b, x, xf, 256, 256);
    // 5) LN2 -> fp16 y2
    ln_kernel<<<NTOK / 8, 256>>>(xf, ln2_g, ln2_b, y2);
    // 6) h = gelu(y2 @ W1 + b1) -> fp16
    gemm_f16<2><<<dim3(8, NTOK / 128), 128>>>(y2, wbuf + W_FFN1, ffn_b1, nullptr, h, 1024, 256);
    // 7) out = h @ W2 + b2 + xf -> fp32 d_out
    gemm_f16<3><<<dim3(2, NTOK / 128), 128>>>(h, wbuf + W_FFN2, ffn_b2, xf, (float*)d_out, 256, 1024);
}

// round 12
// speedup vs baseline: 1.7909x; 1.1552x over previous
#include <cuda_runtime.h>
#include <cuda_fp16.h>
#include <cstdint>

// ---------------------------------------------------------------------------
// Problem constants
// ---------------------------------------------------------------------------
#define NTOK   204800          // B*T*V = 64*128*25
#define NGRP   8192            // B*T
#define VTOK   25

// ---------------------------------------------------------------------------
// Device scratch (static; no allocation allowed)
// ---------------------------------------------------------------------------
__device__ __half g_y  [(size_t)NTOK * 256];     // LN1 out (GEMM A)
__device__ __half g_qkv[(size_t)NTOK * 768];     // QKV out
__device__ __half g_ao [(size_t)NTOK * 256];     // attention out (GEMM A)
__device__ float  g_xf [(size_t)NTOK * 256];     // residual stream (fp32)
__device__ __half g_y2 [(size_t)NTOK * 256];     // LN2 out (GEMM A)
__device__ __half g_h  [(size_t)NTOK * 1024];    // GELU out (GEMM A)
// transposed + fp16-rounded weights, stored [N][K] K-major
#define W_QKV  0
#define W_PROJ (256 * 768)
#define W_FFN1 (W_PROJ + 256 * 256)
#define W_FFN2 (W_FFN1 + 256 * 1024)
#define W_TOT  (W_FFN2 + 1024 * 256)
__device__ __half g_w[(size_t)W_TOT];

// ---------------------------------------------------------------------------
// Helpers
// ---------------------------------------------------------------------------
__device__ __forceinline__ float gelu_exact(float x) {
    return 0.5f * x * (1.0f + erff(x * 0.70710678118654752f));
}

__device__ __forceinline__ void cp16(unsigned dst, const void* src) {
    asm volatile("cp.async.cg.shared.global [%0], [%1], 16;" :: "r"(dst), "l"(src));
}
#define CP_COMMIT() asm volatile("cp.async.commit_group;")
#define CP_WAIT1()  asm volatile("cp.async.wait_group 1;" ::: "memory")

// fp16 MMA m16n8k16: D(f32) += A(f16) x B(f16)
__device__ __forceinline__ void mma_f16(float* d, const unsigned* a, const unsigned* b) {
    asm volatile(
        "mma.sync.aligned.m16n8k16.row.col.f32.f16.f16.f32 "
        "{%0,%1,%2,%3}, {%4,%5,%6,%7}, {%8,%9}, {%0,%1,%2,%3};"
        : "+f"(d[0]), "+f"(d[1]), "+f"(d[2]), "+f"(d[3])
        : "r"(a[0]), "r"(a[1]), "r"(a[2]), "r"(a[3]), "r"(b[0]), "r"(b[1]));
}

__device__ __forceinline__ void ldsm_x4(unsigned* r, unsigned addr) {
    asm volatile("ldmatrix.sync.aligned.m8n8.x4.shared.b16 {%0,%1,%2,%3}, [%4];"
                 : "=r"(r[0]), "=r"(r[1]), "=r"(r[2]), "=r"(r[3]) : "r"(addr));
}

// ---------------------------------------------------------------------------
// Weight transpose + fp16 rounding: dst[n*K + k] = half(src[k*N + n])
// ---------------------------------------------------------------------------
__global__ __launch_bounds__(256)
void transpose_round(const float* __restrict__ src, __half* __restrict__ dst,
                     int K, int N)
{
    __shared__ float t[32][33];
    int n0 = blockIdx.x * 32, k0 = blockIdx.y * 32;
    int tx = threadIdx.x & 31, ty = threadIdx.x >> 5;   // 32 x 8
    #pragma unroll
    for (int i = 0; i < 4; i++)
        t[ty + i * 8][tx] = src[(long)(k0 + ty + i * 8) * N + n0 + tx];
    __syncthreads();
    #pragma unroll
    for (int i = 0; i < 4; i++)
        dst[(long)(n0 + ty + i * 8) * K + k0 + tx] = __float2half_rn(t[tx][ty + i * 8]);
}

// ---------------------------------------------------------------------------
// LayerNorm: one warp per row of 256. Output fp16 (GEMM A operand).
// ---------------------------------------------------------------------------
__global__ __launch_bounds__(256)
void ln_kernel(const float* __restrict__ x, const float* __restrict__ g,
               const float* __restrict__ b, __half* __restrict__ y)
{
    int row  = blockIdx.x * 8 + (threadIdx.x >> 5);
    int lane = threadIdx.x & 31;
    const float* xr = x + (size_t)row * 256;

    float4 v0 = *(const float4*)(xr + lane * 4);
    float4 v1 = *(const float4*)(xr + 128 + lane * 4);

    float s = v0.x + v0.y + v0.z + v0.w + v1.x + v1.y + v1.z + v1.w;
    #pragma unroll
    for (int o = 16; o; o >>= 1) s += __shfl_xor_sync(0xFFFFFFFFu, s, o);
    float mean = s * (1.0f / 256.0f);

    float d0 = v0.x - mean, d1 = v0.y - mean, d2 = v0.z - mean, d3 = v0.w - mean;
    float d4 = v1.x - mean, d5 = v1.y - mean, d6 = v1.z - mean, d7 = v1.w - mean;
    float vs = d0*d0 + d1*d1 + d2*d2 + d3*d3 + d4*d4 + d5*d5 + d6*d6 + d7*d7;
    #pragma unroll
    for (int o = 16; o; o >>= 1) vs += __shfl_xor_sync(0xFFFFFFFFu, vs, o);
    float rstd = rsqrtf(vs * (1.0f / 256.0f) + 1e-5f);

    float4 g0 = *(const float4*)(g + lane * 4);
    float4 g1 = *(const float4*)(g + 128 + lane * 4);
    float4 b0 = *(const float4*)(b + lane * 4);
    float4 b1 = *(const float4*)(b + 128 + lane * 4);

    __half2* yr = (__half2*)(y + (size_t)row * 256);
    yr[lane * 2]          = __floats2half2_rn(d0 * rstd * g0.x + b0.x, d1 * rstd * g0.y + b0.y);
    yr[lane * 2 + 1]      = __floats2half2_rn(d2 * rstd * g0.z + b0.z, d3 * rstd * g0.w + b0.w);
    yr[64 + lane * 2]     = __floats2half2_rn(d4 * rstd * g1.x + b1.x, d5 * rstd * g1.y + b1.y);
    yr[64 + lane * 2 + 1] = __floats2half2_rn(d6 * rstd * g1.z + b1.z, d7 * rstd * g1.w + b1.w);
}

// ---------------------------------------------------------------------------
// fp16 tensor GEMM v3: C[M,N] = A[M,K](f16) @ Wt[N,K](f16)^T + epilogue
//   EPI 1: +bias -> fp16 C | EPI 2: +bias, GELU -> fp16 C
//   EPI 3: +bias+resid -> fp32 C
// CTA 128x128, 4 warps (2x2) of 64x64, mma m16n8k16 via ldmatrix.x4.
// K-chunk 32, 3-stage cp.async pipeline in dynamic smem, prefetch-before-
// compute (~2 iterations of latency cover). Pitch 20 words, conflict-free.
// ---------------------------------------------------------------------------
#define PITCH  20               // 32-bit words per tile row (16 data + 4 pad)
#define TILE_W (128 * PITCH)    // words per tile (A or B)
#define ST_W   (2 * TILE_W)     // words per stage (A+B)
#define SMEM_G (3 * ST_W * 4)   // bytes: 61440

template<int EPI>
__global__ __launch_bounds__(128, 2)
void gemm_f16(const __half* __restrict__ A, const __half* __restrict__ W,
              const float* __restrict__ bias, const float* __restrict__ resid,
              void* __restrict__ Cv, int N, int K)
{
    extern __shared__ unsigned sm[];

    int tid  = threadIdx.x;
    int w    = tid >> 5;
    int lane = tid & 31;
    int g    = lane >> 2;
    int t    = lane & 3;
    int wm   = w >> 1;      // 0..1
    int wn   = w & 1;       // 0..1

    long mBase = (long)blockIdx.y * 128;
    int  nBase = blockIdx.x * 128;

    const __half* Ab = A + mBase * (long)K;
    const __half* Wb = W + (long)nBase * K;
    unsigned smb = (unsigned)__cvta_generic_to_shared(sm);

    float acc[4][8][4];
    #pragma unroll
    for (int mt = 0; mt < 4; mt++)
        #pragma unroll
        for (int nt = 0; nt < 8; nt++)
            #pragma unroll
            for (int c = 0; c < 4; c++) acc[mt][nt][c] = 0.0f;

    int TC = K >> 5;                 // number of K=32 chunks

    // cp.async: per tile 512 16B-chunks (128 rows x 4 quarters); 128 thr ->
    // 4 chunks A + 4 chunks B each.
    #define LOAD(c)                                                        \
    {                                                                      \
        unsigned st = smb + (unsigned)((c) % 3) * (ST_W * 4u);             \
        const __half* ap = Ab + (c) * 32;                                  \
        const __half* bp = Wb + (c) * 32;                                  \
        _Pragma("unroll")                                                  \
        for (int i = 0; i < 4; i++) {                                      \
            int ch = tid + i * 128;                                        \
            int r = ch >> 2, q = ch & 3;                                   \
            unsigned so = (unsigned)((r * PITCH + q * 4) * 4);             \
            long     go = (long)r * K + q * 8;                             \
            cp16(st + so, ap + go);                                        \
            cp16(st + TILE_W * 4u + so, bp + go);                          \
        }                                                                  \
    }

    LOAD(0); CP_COMMIT();
    LOAD(1); CP_COMMIT();

    // ldmatrix lane addressing
    int rowA  = (lane & 7) + ((lane >> 3) & 1) * 8;   // m within 16-row tile
    int halfA = lane >> 4;                            // 16B half within k16
    int rowB  = (lane & 7) + (lane >> 4) * 8;         // n within 16-row pair
    int halfB = (lane >> 3) & 1;

    for (int c = 0; c < TC; c++) {
        CP_WAIT1();
        __syncthreads();

        if (c + 2 < TC) LOAD(c + 2);
        CP_COMMIT();

        unsigned sa = smb + (unsigned)(c % 3) * (ST_W * 4u);
        unsigned sb = sa + TILE_W * 4u;

        #pragma unroll
        for (int sub = 0; sub < 2; sub++) {
            unsigned kw = (unsigned)(sub * 8);

            unsigned af[4][4];
            #pragma unroll
            for (int mt = 0; mt < 4; mt++)
                ldsm_x4(af[mt], sa + (((wm * 64 + mt * 16 + rowA) * PITCH + kw + halfA * 4) * 4));

            unsigned bf[8][2];
            #pragma unroll
            for (int p = 0; p < 4; p++) {
                unsigned r[4];
                ldsm_x4(r, sb + (((wn * 64 + p * 16 + rowB) * PITCH + kw + halfB * 4) * 4));
                bf[2*p][0] = r[0]; bf[2*p][1] = r[1];
                bf[2*p+1][0] = r[2]; bf[2*p+1][1] = r[3];
            }

            #pragma unroll
            for (int mt = 0; mt < 4; mt++)
                #pragma unroll
                for (int nt = 0; nt < 8; nt++)
                    mma_f16(acc[mt][nt], af[mt], bf[nt]);
        }
    }
    #undef LOAD

    // ---- epilogue ----
    #pragma unroll
    for (int mt = 0; mt < 4; mt++) {
        long r0 = mBase + wm * 64 + mt * 16 + g;
        long r1 = r0 + 8;
        #pragma unroll
        for (int nt = 0; nt < 8; nt++) {
            int cb = nBase + wn * 64 + nt * 8 + t * 2;
            float bb0 = bias[cb], bb1 = bias[cb + 1];
            float c0 = acc[mt][nt][0] + bb0;
            float c1 = acc[mt][nt][1] + bb1;
            float c2 = acc[mt][nt][2] + bb0;
            float c3 = acc[mt][nt][3] + bb1;
            if (EPI == 1) {          // -> fp16 output (qkv)
                __half* C = (__half*)Cv;
                *(__half2*)(C + r0 * N + cb) = __floats2half2_rn(c0, c1);
                *(__half2*)(C + r1 * N + cb) = __floats2half2_rn(c2, c3);
            } else if (EPI == 2) {   // GELU -> fp16 output
                __half* C = (__half*)Cv;
                *(__half2*)(C + r0 * N + cb) =
                    __floats2half2_rn(gelu_exact(c0), gelu_exact(c1));
                *(__half2*)(C + r1 * N + cb) =
                    __floats2half2_rn(gelu_exact(c2), gelu_exact(c3));
            } else {                 // +resid -> fp32 output
                float* C = (float*)Cv;
                float2 ra = *(const float2*)(resid + r0 * N + cb);
                float2 rb = *(const float2*)(resid + r1 * N + cb);
                float2 o0; o0.x = c0 + ra.x; o0.y = c1 + ra.y;
                float2 o1; o1.x = c2 + rb.x; o1.y = c3 + rb.y;
                *(float2*)(C + r0 * N + cb) = o0;
                *(float2*)(C + r1 * N + cb) = o1;
            }
        }
    }
}

// ---------------------------------------------------------------------------
// Cosine attention. One block = (group, half); 4 warps = 4 heads.
// Reads fp16 qkv (converted to fp32 in smem); writes fp16 ao.
// ---------------------------------------------------------------------------
#define SQ_STRIDE 388

__global__ __launch_bounds__(128)
void attn_kernel(const __half* __restrict__ qkv, const float* __restrict__ ls,
                 __half* __restrict__ ao)
{
    __shared__ float sq[VTOK * SQ_STRIDE];

    int g    = blockIdx.x >> 1;
    int half = blockIdx.x & 1;
    int tid  = threadIdx.x;

    const __half* src = qkv + (size_t)g * VTOK * 768 + half * 128;
    for (int idx = tid; idx < VTOK * 48; idx += 128) {
        int r = idx / 48, rem = idx % 48;
        int s = rem >> 4, c8 = rem & 15;
        const __half2* p = (const __half2*)(src + (size_t)r * 768 + s * 256 + c8 * 8);
        float* dst = sq + r * SQ_STRIDE + s * 128 + c8 * 8;
        #pragma unroll
        for (int u = 0; u < 4; u++) {
            float2 f = __half22float2(p[u]);
            dst[u * 2] = f.x; dst[u * 2 + 1] = f.y;
        }
    }
    __syncthreads();

    int w    = tid >> 5;
    int lane = tid & 31;
    int h    = half * 4 + w;

    float scale = __expf(fminf(ls[h], 4.60517018598809f));   // log(100)

    if (lane < VTOK) {
        float* kr = sq + lane * SQ_STRIDE + 128 + w * 32;
        float kv[32];
        float ss = 0.0f;
        #pragma unroll
        for (int c = 0; c < 8; c++) {
            float4 t4 = *(const float4*)(kr + c * 4);
            kv[c*4+0] = t4.x; kv[c*4+1] = t4.y; kv[c*4+2] = t4.z; kv[c*4+3] = t4.w;
            ss += t4.x*t4.x + t4.y*t4.y + t4.z*t4.z + t4.w*t4.w;
        }
        float inv = 1.0f / fmaxf(sqrtf(ss), 1e-12f);
        #pragma unroll
        for (int c = 0; c < 8; c++) {
            float4 t4;
            t4.x = kv[c*4+0]*inv; t4.y = kv[c*4+1]*inv;
            t4.z = kv[c*4+2]*inv; t4.w = kv[c*4+3]*inv;
            *(float4*)(kr + c * 4) = t4;
        }
    }
    __syncwarp();

    int i = lane < VTOK ? lane : 0;
    const float* qr = sq + i * SQ_STRIDE + w * 32;
    float q[32];
    float ss = 0.0f;
    #pragma unroll
    for (int c = 0; c < 8; c++) {
        float4 t4 = *(const float4*)(qr + c * 4);
        q[c*4+0] = t4.x; q[c*4+1] = t4.y; q[c*4+2] = t4.z; q[c*4+3] = t4.w;
        ss += t4.x*t4.x + t4.y*t4.y + t4.z*t4.z + t4.w*t4.w;
    }
    float qf = scale / (5.65685424949238f * fmaxf(sqrtf(ss), 1e-12f));
    #pragma unroll
    for (int d = 0; d < 32; d++) q[d] *= qf;

    float p[VTOK];
    #pragma unroll
    for (int j = 0; j < VTOK; j++) {
        const float* kr = sq + j * SQ_STRIDE + 128 + w * 32;
        float a = 0.0f;
        #pragma unroll
        for (int c = 0; c < 8; c++) {
            float4 k4 = *(const float4*)(kr + c * 4);
            a += q[c*4+0]*k4.x + q[c*4+1]*k4.y + q[c*4+2]*k4.z + q[c*4+3]*k4.w;
        }
        p[j] = a;
    }

    float m = p[0];
    #pragma unroll
    for (int j = 1; j < VTOK; j++) m = fmaxf(m, p[j]);
    float s = 0.0f;
    #pragma unroll
    for (int j = 0; j < VTOK; j++) { p[j] = __expf(p[j] - m); s += p[j]; }
    float invs = 1.0f / s;

    float o[32];
    #pragma unroll
    for (int d = 0; d < 32; d++) o[d] = 0.0f;
    #pragma unroll
    for (int j = 0; j < VTOK; j++) {
        const float* vr = sq + j * SQ_STRIDE + 256 + w * 32;
        float pj = p[j] * invs;
        #pragma unroll
        for (int c = 0; c < 8; c++) {
            float4 v4 = *(const float4*)(vr + c * 4);
            o[c*4+0] += pj * v4.x; o[c*4+1] += pj * v4.y;
            o[c*4+2] += pj * v4.z; o[c*4+3] += pj * v4.w;
        }
    }

    if (lane < VTOK) {
        __half2* dst = (__half2*)(ao + ((size_t)g * VTOK + lane) * 256 + h * 32);
        #pragma unroll
        for (int c = 0; c < 8; c++) {
            dst[c * 2]     = __floats2half2_rn(o[c*4+0], o[c*4+1]);
            dst[c * 2 + 1] = __floats2half2_rn(o[c*4+2], o[c*4+3]);
        }
    }
}

// ---------------------------------------------------------------------------
// Launch
// ---------------------------------------------------------------------------
extern "C" void kernel_launch(void* const* d_in, const int* in_sizes, int n_in,
                              void* d_out, int out_size)
{
    const float* x       = (const float*)d_in[0];
    const float* ln1_g   = (const float*)d_in[1];
    const float* ln1_b   = (const float*)d_in[2];
    const float* qkv_w   = (const float*)d_in[3];
    const float* qkv_b   = (const float*)d_in[4];
    const float* proj_w  = (const float*)d_in[5];
    const float* proj_b  = (const float*)d_in[6];
    const float* lscale  = (const float*)d_in[7];
    const float* ln2_g   = (const float*)d_in[8];
    const float* ln2_b   = (const float*)d_in[9];
    const float* ffn_w1  = (const float*)d_in[10];
    const float* ffn_b1  = (const float*)d_in[11];
    const float* ffn_w2  = (const float*)d_in[12];
    const float* ffn_b2  = (const float*)d_in[13];

    __half *y, *qkv, *ao, *y2, *h, *wbuf;
    float  *xf;
    cudaGetSymbolAddress((void**)&y,    g_y);
    cudaGetSymbolAddress((void**)&qkv,  g_qkv);
    cudaGetSymbolAddress((void**)&ao,   g_ao);
    cudaGetSymbolAddress((void**)&xf,   g_xf);
    cudaGetSymbolAddress((void**)&y2,   g_y2);
    cudaGetSymbolAddress((void**)&h,    g_h);
    cudaGetSymbolAddress((void**)&wbuf, g_w);

    cudaFuncSetAttribute(gemm_f16<1>, cudaFuncAttributeMaxDynamicSharedMemorySize, SMEM_G);
    cudaFuncSetAttribute(gemm_f16<2>, cudaFuncAttributeMaxDynamicSharedMemorySize, SMEM_G);
    cudaFuncSetAttribute(gemm_f16<3>, cudaFuncAttributeMaxDynamicSharedMemorySize, SMEM_G);

    // 0) weights -> transposed [N][K] fp16
    transpose_round<<<dim3(768 / 32, 256 / 32), 256>>>(qkv_w,  wbuf + W_QKV,  256, 768);
    transpose_round<<<dim3(256 / 32, 256 / 32), 256>>>(proj_w, wbuf + W_PROJ, 256, 256);
    transpose_round<<<dim3(1024 / 32, 256 / 32), 256>>>(ffn_w1, wbuf + W_FFN1, 256, 1024);
    transpose_round<<<dim3(256 / 32, 1024 / 32), 256>>>(ffn_w2, wbuf + W_FFN2, 1024, 256);

    // 1) LN1 -> fp16 y
    ln_kernel<<<NTOK / 8, 256>>>(x, ln1_g, ln1_b, y);
    // 2) QKV = y @ Wqkv + b  -> fp16 qkv
    gemm_f16<1><<<dim3(6, NTOK / 128), 128, SMEM_G>>>(y, wbuf + W_QKV, qkv_b, nullptr, qkv, 768, 256);
    // 3) cosine attention -> fp16 ao
    attn_kernel<<<NGRP * 2, 128>>>(qkv, lscale, ao);
    // 4) xf = ao @ Wproj + b + x  -> fp32
    gemm_f16<3><<<dim3(2, NTOK / 128), 128, SMEM_G>>>(ao, wbuf + W_PROJ, proj_b, x, xf, 256, 256);
    // 5) LN2 -> fp16 y2
    ln_kernel<<<NTOK / 8, 256>>>(xf, ln2_g, ln2_b, y2);
    // 6) h = gelu(y2 @ W1 + b1) -> fp16
    gemm_f16<2><<<dim3(8, NTOK / 128), 128, SMEM_G>>>(y2, wbuf + W_FFN1, ffn_b1, nullptr, h, 1024, 256);
    // 7) out = h @ W2 + b2 + xf -> fp32 d_out
    gemm_f16<3><<<dim3(2, NTOK / 128), 128, SMEM_G>>>(h, wbuf + W_FFN2, ffn_b2, xf, (float*)d_out, 256, 1024);
}